// round 6
// baseline (speedup 1.0000x reference)
#include <cuda_runtime.h>
#include <math.h>
#include <stdint.h>

// Problem dims
#define BB   8
#define HH   96
#define WW   96
#define CCH  512
#define DD   64
#define LL   192
#define NPOS (BB*HH*WW)   // 73728

// ---------------------------------------------------------------------------
// Scratch (device globals)
// ---------------------------------------------------------------------------
__device__ float g_qk[(size_t)NPOS*128];    // q | k packed, tf32-rounded
__device__ float g_v [(size_t)NPOS*CCH];    // tf32-rounded
__device__ float g_S [(size_t)NPOS*LL];     // raw scores (diag masked)
__device__ float g_yv[(size_t)NPOS*CCH];
__device__ float g_xt[(size_t)NPOS*CCH];    // tf32-rounded x
__device__ float g_wvt [(size_t)CCH*CCH];   // tf32-rounded Wv
__device__ float g_wqkt[(size_t)CCH*128];   // tf32-rounded [Wq|Wk]
__device__ float g_bqk [128];

// ---------------------------------------------------------------------------
// Helpers (baseline PTX, sm_80+)
// ---------------------------------------------------------------------------
__device__ __forceinline__ uint32_t smem_u32(const void* p) {
    uint32_t a;
    asm("{ .reg .u64 t; cvta.to.shared.u64 t, %1; cvt.u32.u64 %0, t; }" : "=r"(a) : "l"(p));
    return a;
}
__device__ __forceinline__ uint32_t f2tf32(float f) {
    uint32_t r;
    asm("cvt.rna.tf32.f32 %0, %1;" : "=r"(r) : "f"(f));
    return r;
}
__device__ __forceinline__ void mma_tf32(
    float& c0, float& c1, float& c2, float& c3,
    uint32_t a0, uint32_t a1, uint32_t a2, uint32_t a3,
    uint32_t b0, uint32_t b1)
{
    asm volatile(
        "mma.sync.aligned.m16n8k8.row.col.f32.tf32.tf32.f32 "
        "{%0,%1,%2,%3}, {%4,%5,%6,%7}, {%8,%9}, {%0,%1,%2,%3};"
        : "+f"(c0), "+f"(c1), "+f"(c2), "+f"(c3)
        : "r"(a0), "r"(a1), "r"(a2), "r"(a3), "r"(b0), "r"(b1));
}
__device__ __forceinline__ void cpasync16(uint32_t dst, const void* src) {
    asm volatile("cp.async.cg.shared.global [%0], [%1], 16;" :: "r"(dst), "l"(src));
}
#define CP_COMMIT() asm volatile("cp.async.commit_group;" ::: "memory")
#define CP_WAIT(n)  asm volatile("cp.async.wait_group %0;" :: "n"(n) : "memory")

// ---------------------------------------------------------------------------
// P0: tf32 pre-round
// ---------------------------------------------------------------------------
__global__ __launch_bounds__(256) void round_tf32_kernel(
    const float* __restrict__ src, float* __restrict__ dst, size_t n4)
{
    size_t i = (size_t)blockIdx.x * 256 + threadIdx.x;
    if (i >= n4) return;
    float4 v = *reinterpret_cast<const float4*>(src + i * 4);
    float4 o;
    o.x = __uint_as_float(f2tf32(v.x));
    o.y = __uint_as_float(f2tf32(v.y));
    o.z = __uint_as_float(f2tf32(v.z));
    o.w = __uint_as_float(f2tf32(v.w));
    *reinterpret_cast<float4*>(dst + i * 4) = o;
}

// P1: build combined rounded [Wq|Wk] and bias
__global__ __launch_bounds__(256) void prep_qk_kernel(
    const float* __restrict__ Wq, const float* __restrict__ Wk,
    const float* __restrict__ bq, const float* __restrict__ bk)
{
    int idx = blockIdx.x * 256 + threadIdx.x;
    if (idx < CCH * 128) {
        int k = idx >> 7, j = idx & 127;
        float v = (j < 64) ? Wq[k * 64 + j] : Wk[k * 64 + (j - 64)];
        g_wqkt[idx] = __uint_as_float(f2tf32(v));
    }
    if (blockIdx.x == 0 && threadIdx.x < 128) {
        int j = threadIdx.x;
        g_bqk[j] = (j < 64) ? bq[j] : bk[j - 64];
    }
}

// ---------------------------------------------------------------------------
// K1: tf32 projection GEMM (pre-rounded operands)
//   BM=128, BK=32, BN=128. 256 thr = 8 warps (2m x 4n). Output tf32-rounded.
// ---------------------------------------------------------------------------
#define P_AP 36
#define P_BP 136
#define P_ASZ (128*P_AP)
#define P_BSZ (32*P_BP)
#define P_SMEM ((P_ASZ + P_BSZ) * 2 * 4)

__global__ __launch_bounds__(256) void proj_mma(
    const float* __restrict__ X, const float* __restrict__ W,
    const float* __restrict__ bias, float* __restrict__ C, int M)
{
    constexpr int BN = 128, BK = 32, NCH = CCH / BK;
    extern __shared__ float sm[];
    const uint32_t sbase = smem_u32(sm);
    const int tid = threadIdx.x;
    const int wid = tid >> 5, lane = tid & 31;
    const int gid = lane >> 2, tg = lane & 3;
    const int wm = wid >> 2, wn = wid & 3;
    const int rowBase = blockIdx.y * 128;
    const int n0 = blockIdx.x * BN;

    float acc[4][4][4];
    #pragma unroll
    for (int mt = 0; mt < 4; mt++)
        #pragma unroll
        for (int nt = 0; nt < 4; nt++)
            #pragma unroll
            for (int i = 0; i < 4; i++) acc[mt][nt][i] = 0.f;

    auto issue = [&](int ch, int buf) {
        const int kc = ch * BK;
        const uint32_t abase = sbase + (uint32_t)(buf * (P_ASZ + P_BSZ)) * 4u;
        const uint32_t bbase = abase + (uint32_t)P_ASZ * 4u;
        #pragma unroll
        for (int i = 0; i < 4; i++) {
            int idx = tid + i * 256;
            int r = idx >> 3, c4 = idx & 7;
            cpasync16(abase + (uint32_t)(r * P_AP + c4 * 4) * 4u,
                      &X[(size_t)(rowBase + r) * CCH + kc + c4 * 4]);
        }
        #pragma unroll
        for (int i = 0; i < 4; i++) {
            int idx = tid + i * 256;
            int kr = idx >> 5, c4 = idx & 31;
            cpasync16(bbase + (uint32_t)(kr * P_BP + c4 * 4) * 4u,
                      &W[(size_t)(kc + kr) * M + n0 + c4 * 4]);
        }
        CP_COMMIT();
    };

    issue(0, 0);
    for (int ch = 0; ch < NCH; ch++) {
        const int buf = ch & 1;
        if (ch + 1 < NCH) { issue(ch + 1, buf ^ 1); CP_WAIT(1); }
        else              { CP_WAIT(0); }
        __syncthreads();

        const float* Ab = sm + buf * (P_ASZ + P_BSZ);
        const float* Bb = Ab + P_ASZ;
        #pragma unroll
        for (int ks = 0; ks < 4; ks++) {
            const int k0 = ks * 8;
            uint32_t a[4][4];
            #pragma unroll
            for (int mt = 0; mt < 4; mt++) {
                const int m = wm * 64 + mt * 16;
                a[mt][0] = __float_as_uint(Ab[(m + gid)     * P_AP + k0 + tg]);
                a[mt][1] = __float_as_uint(Ab[(m + 8 + gid) * P_AP + k0 + tg]);
                a[mt][2] = __float_as_uint(Ab[(m + gid)     * P_AP + k0 + tg + 4]);
                a[mt][3] = __float_as_uint(Ab[(m + 8 + gid) * P_AP + k0 + tg + 4]);
            }
            uint32_t b[4][2];
            #pragma unroll
            for (int nt = 0; nt < 4; nt++) {
                const int col = wn * 32 + nt * 8 + gid;
                b[nt][0] = __float_as_uint(Bb[(k0 + tg)     * P_BP + col]);
                b[nt][1] = __float_as_uint(Bb[(k0 + tg + 4) * P_BP + col]);
            }
            #pragma unroll
            for (int mt = 0; mt < 4; mt++)
                #pragma unroll
                for (int nt = 0; nt < 4; nt++)
                    mma_tf32(acc[mt][nt][0], acc[mt][nt][1], acc[mt][nt][2], acc[mt][nt][3],
                             a[mt][0], a[mt][1], a[mt][2], a[mt][3],
                             b[nt][0], b[nt][1]);
        }
        __syncthreads();
    }

    #pragma unroll
    for (int mt = 0; mt < 4; mt++) {
        const int row = rowBase + wm * 64 + mt * 16 + gid;
        #pragma unroll
        for (int nt = 0; nt < 4; nt++) {
            const int col = n0 + wn * 32 + nt * 8 + tg * 2;
            const float b0 = bias[col], b1 = bias[col + 1];
            C[(size_t)row * M + col]           = __uint_as_float(f2tf32(acc[mt][nt][0] + b0));
            C[(size_t)row * M + col + 1]       = __uint_as_float(f2tf32(acc[mt][nt][1] + b1));
            C[(size_t)(row + 8) * M + col]     = __uint_as_float(f2tf32(acc[mt][nt][2] + b0));
            C[(size_t)(row + 8) * M + col + 1] = __uint_as_float(f2tf32(acc[mt][nt][3] + b1));
        }
    }
}

// ---------------------------------------------------------------------------
// K2/K3: score GEMMs on mma. Q,K tiles [96 x 64] tf32.
//   MASK: diag mask (sv). SOFF: output col offset (0 sv / 96 sh).
//   sv: block (w,b), rows=h, cols=g.   sh: block (h,b), rows=w, cols=u.
// ---------------------------------------------------------------------------
#define SC_P 68
#define SC_SMEM (2*96*SC_P*4)    // 52224

template<bool SV>
__global__ __launch_bounds__(256) void score_mma() {
    extern __shared__ float sm[];
    float* Qs = sm;
    float* Ks = sm + 96*SC_P;
    const uint32_t sbase = smem_u32(sm);
    const int b = blockIdx.y, line = blockIdx.x;   // w (sv) or h (sh)
    const int tid = threadIdx.x;
    const int wid = tid >> 5, lane = tid & 31;
    const int gid = lane >> 2, tg = lane & 3;
    const int wm = wid >> 2, wn = wid & 3;

    for (int i = tid; i < 96*16; i += 256) {
        int r = i >> 4, c4 = i & 15;
        size_t src = SV
            ? ((size_t)((b*HH + r)*WW) + line)*128    // column w=line, row h=r
            : ((size_t)((b*HH + line)*WW) + r)*128;   // row h=line, col w=r
        cpasync16(sbase + (uint32_t)(r*SC_P + c4*4)*4u,            &g_qk[src + c4*4]);
        cpasync16(sbase + (uint32_t)(96*SC_P + r*SC_P + c4*4)*4u,  &g_qk[src + 64 + c4*4]);
    }
    CP_COMMIT(); CP_WAIT(0);
    __syncthreads();

    float acc[3][3][4];
    #pragma unroll
    for (int mt = 0; mt < 3; mt++)
        #pragma unroll
        for (int nt = 0; nt < 3; nt++)
            #pragma unroll
            for (int i = 0; i < 4; i++) acc[mt][nt][i] = 0.f;

    #pragma unroll
    for (int ks = 0; ks < 8; ks++) {
        const int k0 = ks * 8;
        uint32_t a[3][4];
        #pragma unroll
        for (int mt = 0; mt < 3; mt++) {
            const int m = wm * 48 + mt * 16;
            a[mt][0] = __float_as_uint(Qs[(m + gid)     * SC_P + k0 + tg]);
            a[mt][1] = __float_as_uint(Qs[(m + 8 + gid) * SC_P + k0 + tg]);
            a[mt][2] = __float_as_uint(Qs[(m + gid)     * SC_P + k0 + tg + 4]);
            a[mt][3] = __float_as_uint(Qs[(m + 8 + gid) * SC_P + k0 + tg + 4]);
        }
        uint32_t bf[3][2];
        #pragma unroll
        for (int nt = 0; nt < 3; nt++) {
            const int col = wn * 24 + nt * 8 + gid;
            bf[nt][0] = __float_as_uint(Ks[col * SC_P + k0 + tg]);
            bf[nt][1] = __float_as_uint(Ks[col * SC_P + k0 + tg + 4]);
        }
        #pragma unroll
        for (int mt = 0; mt < 3; mt++)
            #pragma unroll
            for (int nt = 0; nt < 3; nt++)
                mma_tf32(acc[mt][nt][0], acc[mt][nt][1], acc[mt][nt][2], acc[mt][nt][3],
                         a[mt][0], a[mt][1], a[mt][2], a[mt][3],
                         bf[nt][0], bf[nt][1]);
    }

    #pragma unroll
    for (int mt = 0; mt < 3; mt++) {
        const int r0 = wm * 48 + mt * 16 + gid;
        #pragma unroll
        for (int nt = 0; nt < 3; nt++) {
            const int c0 = wn * 24 + nt * 8 + tg * 2;
            #pragma unroll
            for (int half = 0; half < 2; half++) {
                const int r = r0 + half * 8;
                size_t base = SV
                    ? ((size_t)((b*HH + r)*WW) + line)*LL
                    : ((size_t)((b*HH + line)*WW) + r)*LL + 96;
                float v0 = acc[mt][nt][half*2],  v1 = acc[mt][nt][half*2 + 1];
                if (SV) {
                    if (c0     == r) v0 = -1e30f;
                    if (c0 + 1 == r) v1 = -1e30f;
                }
                g_S[base + c0]     = v0;
                g_S[base + c0 + 1] = v1;
            }
        }
    }
}

// ---------------------------------------------------------------------------
// K5/K6: attention apply with fused softmax.
//   One block per (line, b). A = full score rows [96 x 192] -> in-block
//   softmax (tf32 probs in smem). Loop 4 V chunks of 128 cols, double-buffered.
//   KOFF selects which half of A feeds the mma (0: yv, 96: yh).
// ---------------------------------------------------------------------------
#define AT_AP 196
#define AT_BP 136
#define AT_ASZ (96*AT_AP)
#define AT_BSZ (96*AT_BP)
#define AT_SMEM ((AT_ASZ + 2*AT_BSZ)*4)   // 179712

template<bool YH>
__global__ __launch_bounds__(256) void apply_mma(
    const float* __restrict__ x, const float* __restrict__ gamma,
    float* __restrict__ out)
{
    extern __shared__ float sm[];
    float* As = sm;
    const uint32_t sbase = smem_u32(sm);
    const int b = blockIdx.y, line = blockIdx.x;
    const int tid = threadIdx.x;
    const int wid = tid >> 5, lane = tid & 31;
    const int gid = lane >> 2, tg = lane & 3;
    const int wm = wid >> 2, wn = wid & 3;
    constexpr int KOFF = YH ? 96 : 0;

    // row index -> global position: yv: (b, r, line) ; yh: (b, line, r)
    auto posOf = [&](int r) -> size_t {
        return YH ? ((size_t)((b*HH + line)*WW) + r)
                  : ((size_t)((b*HH + r)*WW) + line);
    };

    auto issueB = [&](int c, int buf) {
        const uint32_t bbase = sbase + (uint32_t)(AT_ASZ + buf*AT_BSZ)*4u;
        for (int i = tid; i < 96*32; i += 256) {
            int g = i >> 5, c4 = i & 31;
            cpasync16(bbase + (uint32_t)(g*AT_BP + c4*4)*4u,
                      &g_v[posOf(g)*CCH + c*128 + c4*4]);
        }
        CP_COMMIT();
    };

    // A: full 192-wide score rows
    for (int i = tid; i < 96*48; i += 256) {
        int r = i / 48, c4 = i % 48;
        cpasync16(sbase + (uint32_t)(r*AT_AP + c4*4)*4u,
                  &g_S[posOf(r)*LL + c4*4]);
    }
    issueB(0, 0);           // group 0 = A + B0
    issueB(1, 1);           // group 1 = B1
    CP_WAIT(1);             // A + B0 ready
    __syncthreads();

    // In-block softmax over each 192-row; write tf32 probs back to smem.
    {
        for (int r = wid * 12; r < wid * 12 + 12; r++) {
            float v[6];
            float mx = -3.4e38f;
            #pragma unroll
            for (int i = 0; i < 6; i++) { v[i] = As[r*AT_AP + lane + 32*i]; mx = fmaxf(mx, v[i]); }
            #pragma unroll
            for (int o = 16; o; o >>= 1) mx = fmaxf(mx, __shfl_xor_sync(0xffffffffu, mx, o));
            float s = 0.f;
            #pragma unroll
            for (int i = 0; i < 6; i++) { v[i] = expf(v[i] - mx); s += v[i]; }
            #pragma unroll
            for (int o = 16; o; o >>= 1) s += __shfl_xor_sync(0xffffffffu, s, o);
            const float inv = 1.f / s;
            #pragma unroll
            for (int i = 0; i < 6; i++)
                As[r*AT_AP + lane + 32*i] = __uint_as_float(f2tf32(v[i] * inv));
        }
    }
    __syncthreads();

    const float gm = YH ? *gamma : 0.f;

    for (int c = 0; c < 4; c++) {
        if (c >= 1) {
            if (c + 1 < 4) { issueB(c + 1, (c + 1) & 1); CP_WAIT(1); }
            else           { CP_WAIT(0); }
            __syncthreads();
        }
        const float* Bs = sm + AT_ASZ + (c & 1)*AT_BSZ;

        float acc[3][4][4];
        #pragma unroll
        for (int mt = 0; mt < 3; mt++)
            #pragma unroll
            for (int nt = 0; nt < 4; nt++)
                #pragma unroll
                for (int i = 0; i < 4; i++) acc[mt][nt][i] = 0.f;

        #pragma unroll
        for (int ks = 0; ks < 12; ks++) {
            const int k0 = ks * 8;
            uint32_t a[3][4];
            #pragma unroll
            for (int mt = 0; mt < 3; mt++) {
                const int m = wm * 48 + mt * 16;
                a[mt][0] = __float_as_uint(As[(m + gid)     * AT_AP + KOFF + k0 + tg]);
                a[mt][1] = __float_as_uint(As[(m + 8 + gid) * AT_AP + KOFF + k0 + tg]);
                a[mt][2] = __float_as_uint(As[(m + gid)     * AT_AP + KOFF + k0 + tg + 4]);
                a[mt][3] = __float_as_uint(As[(m + 8 + gid) * AT_AP + KOFF + k0 + tg + 4]);
            }
            uint32_t bf[4][2];
            #pragma unroll
            for (int nt = 0; nt < 4; nt++) {
                const int col = wn * 32 + nt * 8 + gid;
                bf[nt][0] = __float_as_uint(Bs[(k0 + tg)     * AT_BP + col]);
                bf[nt][1] = __float_as_uint(Bs[(k0 + tg + 4) * AT_BP + col]);
            }
            #pragma unroll
            for (int mt = 0; mt < 3; mt++)
                #pragma unroll
                for (int nt = 0; nt < 4; nt++)
                    mma_tf32(acc[mt][nt][0], acc[mt][nt][1], acc[mt][nt][2], acc[mt][nt][3],
                             a[mt][0], a[mt][1], a[mt][2], a[mt][3],
                             bf[nt][0], bf[nt][1]);
        }

        #pragma unroll
        for (int mt = 0; mt < 3; mt++) {
            const int row0 = wm * 48 + mt * 16 + gid;
            #pragma unroll
            for (int nt = 0; nt < 4; nt++) {
                const int col = c*128 + wn * 32 + nt * 8 + tg * 2;
                #pragma unroll
                for (int half = 0; half < 2; half++) {
                    size_t o = posOf(row0 + half*8)*CCH + col;
                    float c0v = acc[mt][nt][half*2], c1v = acc[mt][nt][half*2 + 1];
                    if (YH) {
                        float2 yv = *reinterpret_cast<const float2*>(&g_yv[o]);
                        float2 xv = *reinterpret_cast<const float2*>(&x[o]);
                        float2 r;
                        r.x = fmaf(c0v + yv.x, gm, xv.x);
                        r.y = fmaf(c1v + yv.y, gm, xv.y);
                        *reinterpret_cast<float2*>(&out[o]) = r;
                    } else {
                        *reinterpret_cast<float2*>(&g_yv[o]) = make_float2(c0v, c1v);
                    }
                }
            }
        }
        __syncthreads();
    }
}

// ---------------------------------------------------------------------------
extern "C" void kernel_launch(void* const* d_in, const int* in_sizes, int n_in,
                              void* d_out, int out_size)
{
    const float* x     = (const float*)d_in[0];
    const float* Wq    = (const float*)d_in[1];
    const float* bq    = (const float*)d_in[2];
    const float* Wk    = (const float*)d_in[3];
    const float* bk    = (const float*)d_in[4];
    const float* Wv    = (const float*)d_in[5];
    const float* bv    = (const float*)d_in[6];
    const float* gamma = (const float*)d_in[7];
    float* out = (float*)d_out;

    float *qkp, *vp, *xt, *wvt, *wqkt, *bqk;
    cudaGetSymbolAddress((void**)&qkp,  g_qk);
    cudaGetSymbolAddress((void**)&vp,   g_v);
    cudaGetSymbolAddress((void**)&xt,   g_xt);
    cudaGetSymbolAddress((void**)&wvt,  g_wvt);
    cudaGetSymbolAddress((void**)&wqkt, g_wqkt);
    cudaGetSymbolAddress((void**)&bqk,  g_bqk);

    cudaFuncSetAttribute(proj_mma,         cudaFuncAttributeMaxDynamicSharedMemorySize, P_SMEM);
    cudaFuncSetAttribute(score_mma<true>,  cudaFuncAttributeMaxDynamicSharedMemorySize, SC_SMEM);
    cudaFuncSetAttribute(score_mma<false>, cudaFuncAttributeMaxDynamicSharedMemorySize, SC_SMEM);
    cudaFuncSetAttribute(apply_mma<false>, cudaFuncAttributeMaxDynamicSharedMemorySize, AT_SMEM);
    cudaFuncSetAttribute(apply_mma<true>,  cudaFuncAttributeMaxDynamicSharedMemorySize, AT_SMEM);

    // Pre-round
    round_tf32_kernel<<<(NPOS*CCH/4 + 255)/256, 256>>>(x,  xt,  (size_t)NPOS*CCH/4);
    round_tf32_kernel<<<(CCH*CCH/4  + 255)/256, 256>>>(Wv, wvt, (size_t)CCH*CCH/4);
    prep_qk_kernel<<<(CCH*128 + 255)/256, 256>>>(Wq, Wk, bq, bk);

    // Projections (outputs tf32-rounded)
    proj_mma<<<dim3(CCH/128, NPOS/128), 256, P_SMEM>>>(xt, wvt,  bv,  vp,  CCH);
    proj_mma<<<dim3(1,       NPOS/128), 256, P_SMEM>>>(xt, wqkt, bqk, qkp, 128);

    // Scores on mma (raw, diag masked in sv)
    score_mma<true> <<<dim3(WW, BB), 256, SC_SMEM>>>();
    score_mma<false><<<dim3(HH, BB), 256, SC_SMEM>>>();

    // Apply with fused softmax
    apply_mma<false><<<dim3(WW, BB), 256, AT_SMEM>>>(x, gamma, out);
    apply_mma<true> <<<dim3(HH, BB), 256, AT_SMEM>>>(x, gamma, out);
}

// round 7
// speedup vs baseline: 1.2710x; 1.2710x over previous
#include <cuda_runtime.h>
#include <math.h>
#include <stdint.h>

// Problem dims
#define BB   8
#define HH   96
#define WW   96
#define CCH  512
#define DD   64
#define LL   192
#define NPOS (BB*HH*WW)   // 73728

// ---------------------------------------------------------------------------
// Scratch (device globals)
// ---------------------------------------------------------------------------
__device__ float g_qk[(size_t)NPOS*128];    // q | k packed, tf32-rounded
__device__ float g_v [(size_t)NPOS*CCH];    // tf32-rounded
__device__ float g_S [(size_t)NPOS*LL];     // scores -> probs (in place)
__device__ float g_yv[(size_t)NPOS*CCH];
__device__ float g_xt[(size_t)NPOS*CCH];    // tf32-rounded x
__device__ float g_wvt [(size_t)CCH*CCH];   // tf32-rounded Wv
__device__ float g_wqkt[(size_t)CCH*128];   // tf32-rounded [Wq|Wk]
__device__ float g_bqk [128];

// ---------------------------------------------------------------------------
// Helpers (baseline PTX, sm_80+)
// ---------------------------------------------------------------------------
__device__ __forceinline__ uint32_t smem_u32(const void* p) {
    uint32_t a;
    asm("{ .reg .u64 t; cvta.to.shared.u64 t, %1; cvt.u32.u64 %0, t; }" : "=r"(a) : "l"(p));
    return a;
}
__device__ __forceinline__ uint32_t f2tf32(float f) {
    uint32_t r;
    asm("cvt.rna.tf32.f32 %0, %1;" : "=r"(r) : "f"(f));
    return r;
}
__device__ __forceinline__ void mma_tf32(
    float& c0, float& c1, float& c2, float& c3,
    uint32_t a0, uint32_t a1, uint32_t a2, uint32_t a3,
    uint32_t b0, uint32_t b1)
{
    asm volatile(
        "mma.sync.aligned.m16n8k8.row.col.f32.tf32.tf32.f32 "
        "{%0,%1,%2,%3}, {%4,%5,%6,%7}, {%8,%9}, {%0,%1,%2,%3};"
        : "+f"(c0), "+f"(c1), "+f"(c2), "+f"(c3)
        : "r"(a0), "r"(a1), "r"(a2), "r"(a3), "r"(b0), "r"(b1));
}
__device__ __forceinline__ void cpasync16(uint32_t dst, const void* src) {
    asm volatile("cp.async.cg.shared.global [%0], [%1], 16;" :: "r"(dst), "l"(src));
}
#define CP_COMMIT() asm volatile("cp.async.commit_group;" ::: "memory")
#define CP_WAIT(n)  asm volatile("cp.async.wait_group %0;" :: "n"(n) : "memory")

// ---------------------------------------------------------------------------
// P0: tf32 pre-round
// ---------------------------------------------------------------------------
__global__ __launch_bounds__(256) void round_tf32_kernel(
    const float* __restrict__ src, float* __restrict__ dst, size_t n4)
{
    size_t i = (size_t)blockIdx.x * 256 + threadIdx.x;
    if (i >= n4) return;
    float4 v = *reinterpret_cast<const float4*>(src + i * 4);
    float4 o;
    o.x = __uint_as_float(f2tf32(v.x));
    o.y = __uint_as_float(f2tf32(v.y));
    o.z = __uint_as_float(f2tf32(v.z));
    o.w = __uint_as_float(f2tf32(v.w));
    *reinterpret_cast<float4*>(dst + i * 4) = o;
}

// P1: build combined rounded [Wq|Wk] and bias
__global__ __launch_bounds__(256) void prep_qk_kernel(
    const float* __restrict__ Wq, const float* __restrict__ Wk,
    const float* __restrict__ bq, const float* __restrict__ bk)
{
    int idx = blockIdx.x * 256 + threadIdx.x;
    if (idx < CCH * 128) {
        int k = idx >> 7, j = idx & 127;
        float v = (j < 64) ? Wq[k * 64 + j] : Wk[k * 64 + (j - 64)];
        g_wqkt[idx] = __uint_as_float(f2tf32(v));
    }
    if (blockIdx.x == 0 && threadIdx.x < 128) {
        int j = threadIdx.x;
        g_bqk[j] = (j < 64) ? bq[j] : bk[j - 64];
    }
}

// ---------------------------------------------------------------------------
// K1: tf32 projection GEMM (pre-rounded operands)
//   BM=128, BK=32, BN=128. 256 thr = 8 warps (2m x 4n). Output tf32-rounded.
// ---------------------------------------------------------------------------
#define P_AP 36
#define P_BP 136
#define P_ASZ (128*P_AP)
#define P_BSZ (32*P_BP)
#define P_SMEM ((P_ASZ + P_BSZ) * 2 * 4)

__global__ __launch_bounds__(256) void proj_mma(
    const float* __restrict__ X, const float* __restrict__ W,
    const float* __restrict__ bias, float* __restrict__ C, int M)
{
    constexpr int BN = 128, BK = 32, NCH = CCH / BK;
    extern __shared__ float sm[];
    const uint32_t sbase = smem_u32(sm);
    const int tid = threadIdx.x;
    const int wid = tid >> 5, lane = tid & 31;
    const int gid = lane >> 2, tg = lane & 3;
    const int wm = wid >> 2, wn = wid & 3;
    const int rowBase = blockIdx.y * 128;
    const int n0 = blockIdx.x * BN;

    float acc[4][4][4];
    #pragma unroll
    for (int mt = 0; mt < 4; mt++)
        #pragma unroll
        for (int nt = 0; nt < 4; nt++)
            #pragma unroll
            for (int i = 0; i < 4; i++) acc[mt][nt][i] = 0.f;

    auto issue = [&](int ch, int buf) {
        const int kc = ch * BK;
        const uint32_t abase = sbase + (uint32_t)(buf * (P_ASZ + P_BSZ)) * 4u;
        const uint32_t bbase = abase + (uint32_t)P_ASZ * 4u;
        #pragma unroll
        for (int i = 0; i < 4; i++) {
            int idx = tid + i * 256;
            int r = idx >> 3, c4 = idx & 7;
            cpasync16(abase + (uint32_t)(r * P_AP + c4 * 4) * 4u,
                      &X[(size_t)(rowBase + r) * CCH + kc + c4 * 4]);
        }
        #pragma unroll
        for (int i = 0; i < 4; i++) {
            int idx = tid + i * 256;
            int kr = idx >> 5, c4 = idx & 31;
            cpasync16(bbase + (uint32_t)(kr * P_BP + c4 * 4) * 4u,
                      &W[(size_t)(kc + kr) * M + n0 + c4 * 4]);
        }
        CP_COMMIT();
    };

    issue(0, 0);
    for (int ch = 0; ch < NCH; ch++) {
        const int buf = ch & 1;
        if (ch + 1 < NCH) { issue(ch + 1, buf ^ 1); CP_WAIT(1); }
        else              { CP_WAIT(0); }
        __syncthreads();

        const float* Ab = sm + buf * (P_ASZ + P_BSZ);
        const float* Bb = Ab + P_ASZ;
        #pragma unroll
        for (int ks = 0; ks < 4; ks++) {
            const int k0 = ks * 8;
            uint32_t a[4][4];
            #pragma unroll
            for (int mt = 0; mt < 4; mt++) {
                const int m = wm * 64 + mt * 16;
                a[mt][0] = __float_as_uint(Ab[(m + gid)     * P_AP + k0 + tg]);
                a[mt][1] = __float_as_uint(Ab[(m + 8 + gid) * P_AP + k0 + tg]);
                a[mt][2] = __float_as_uint(Ab[(m + gid)     * P_AP + k0 + tg + 4]);
                a[mt][3] = __float_as_uint(Ab[(m + 8 + gid) * P_AP + k0 + tg + 4]);
            }
            uint32_t b[4][2];
            #pragma unroll
            for (int nt = 0; nt < 4; nt++) {
                const int col = wn * 32 + nt * 8 + gid;
                b[nt][0] = __float_as_uint(Bb[(k0 + tg)     * P_BP + col]);
                b[nt][1] = __float_as_uint(Bb[(k0 + tg + 4) * P_BP + col]);
            }
            #pragma unroll
            for (int mt = 0; mt < 4; mt++)
                #pragma unroll
                for (int nt = 0; nt < 4; nt++)
                    mma_tf32(acc[mt][nt][0], acc[mt][nt][1], acc[mt][nt][2], acc[mt][nt][3],
                             a[mt][0], a[mt][1], a[mt][2], a[mt][3],
                             b[nt][0], b[nt][1]);
        }
        __syncthreads();
    }

    #pragma unroll
    for (int mt = 0; mt < 4; mt++) {
        const int row = rowBase + wm * 64 + mt * 16 + gid;
        #pragma unroll
        for (int nt = 0; nt < 4; nt++) {
            const int col = n0 + wn * 32 + nt * 8 + tg * 2;
            const float b0 = bias[col], b1 = bias[col + 1];
            C[(size_t)row * M + col]           = __uint_as_float(f2tf32(acc[mt][nt][0] + b0));
            C[(size_t)row * M + col + 1]       = __uint_as_float(f2tf32(acc[mt][nt][1] + b1));
            C[(size_t)(row + 8) * M + col]     = __uint_as_float(f2tf32(acc[mt][nt][2] + b0));
            C[(size_t)(row + 8) * M + col + 1] = __uint_as_float(f2tf32(acc[mt][nt][3] + b1));
        }
    }
}

// ---------------------------------------------------------------------------
// K2/K3: score GEMMs on mma. Q,K tiles [96 x 64] tf32.
//   sv: block (w,b), rows=h, cols=g, diag masked.   sh: block (h,b), rows=w, cols=u.
// ---------------------------------------------------------------------------
#define SC_P 68
#define SC_SMEM (2*96*SC_P*4)    // 52224

template<bool SV>
__global__ __launch_bounds__(256) void score_mma() {
    extern __shared__ float sm[];
    float* Qs = sm;
    float* Ks = sm + 96*SC_P;
    const uint32_t sbase = smem_u32(sm);
    const int b = blockIdx.y, line = blockIdx.x;
    const int tid = threadIdx.x;
    const int wid = tid >> 5, lane = tid & 31;
    const int gid = lane >> 2, tg = lane & 3;
    const int wm = wid >> 2, wn = wid & 3;

    for (int i = tid; i < 96*16; i += 256) {
        int r = i >> 4, c4 = i & 15;
        size_t src = SV
            ? ((size_t)((b*HH + r)*WW) + line)*128
            : ((size_t)((b*HH + line)*WW) + r)*128;
        cpasync16(sbase + (uint32_t)(r*SC_P + c4*4)*4u,            &g_qk[src + c4*4]);
        cpasync16(sbase + (uint32_t)(96*SC_P + r*SC_P + c4*4)*4u,  &g_qk[src + 64 + c4*4]);
    }
    CP_COMMIT(); CP_WAIT(0);
    __syncthreads();

    float acc[3][3][4];
    #pragma unroll
    for (int mt = 0; mt < 3; mt++)
        #pragma unroll
        for (int nt = 0; nt < 3; nt++)
            #pragma unroll
            for (int i = 0; i < 4; i++) acc[mt][nt][i] = 0.f;

    #pragma unroll
    for (int ks = 0; ks < 8; ks++) {
        const int k0 = ks * 8;
        uint32_t a[3][4];
        #pragma unroll
        for (int mt = 0; mt < 3; mt++) {
            const int m = wm * 48 + mt * 16;
            a[mt][0] = __float_as_uint(Qs[(m + gid)     * SC_P + k0 + tg]);
            a[mt][1] = __float_as_uint(Qs[(m + 8 + gid) * SC_P + k0 + tg]);
            a[mt][2] = __float_as_uint(Qs[(m + gid)     * SC_P + k0 + tg + 4]);
            a[mt][3] = __float_as_uint(Qs[(m + 8 + gid) * SC_P + k0 + tg + 4]);
        }
        uint32_t bf[3][2];
        #pragma unroll
        for (int nt = 0; nt < 3; nt++) {
            const int col = wn * 24 + nt * 8 + gid;
            bf[nt][0] = __float_as_uint(Ks[col * SC_P + k0 + tg]);
            bf[nt][1] = __float_as_uint(Ks[col * SC_P + k0 + tg + 4]);
        }
        #pragma unroll
        for (int mt = 0; mt < 3; mt++)
            #pragma unroll
            for (int nt = 0; nt < 3; nt++)
                mma_tf32(acc[mt][nt][0], acc[mt][nt][1], acc[mt][nt][2], acc[mt][nt][3],
                         a[mt][0], a[mt][1], a[mt][2], a[mt][3],
                         bf[nt][0], bf[nt][1]);
    }

    #pragma unroll
    for (int mt = 0; mt < 3; mt++) {
        const int r0 = wm * 48 + mt * 16 + gid;
        #pragma unroll
        for (int nt = 0; nt < 3; nt++) {
            const int c0 = wn * 24 + nt * 8 + tg * 2;
            #pragma unroll
            for (int half = 0; half < 2; half++) {
                const int r = r0 + half * 8;
                size_t base = SV
                    ? ((size_t)((b*HH + r)*WW) + line)*LL
                    : ((size_t)((b*HH + line)*WW) + r)*LL + 96;
                float v0 = acc[mt][nt][half*2],  v1 = acc[mt][nt][half*2 + 1];
                if (SV) {
                    if (c0     == r) v0 = -1e30f;
                    if (c0 + 1 == r) v1 = -1e30f;
                }
                g_S[base + c0]     = v0;
                g_S[base + c0 + 1] = v1;
            }
        }
    }
}

// ---------------------------------------------------------------------------
// K4: softmax over 192, in place; writes tf32-rounded probs.
// ---------------------------------------------------------------------------
__global__ __launch_bounds__(128) void softmax_kernel() {
    const int lane = threadIdx.x & 31;
    const size_t pos = (size_t)blockIdx.x * 4 + (threadIdx.x >> 5);
    float* s = g_S + pos * LL;
    float v[6];
    float m = -3.4e38f;
    #pragma unroll
    for (int i = 0; i < 6; i++) { v[i] = s[lane + 32*i]; m = fmaxf(m, v[i]); }
    #pragma unroll
    for (int o = 16; o; o >>= 1) m = fmaxf(m, __shfl_xor_sync(0xffffffffu, m, o));
    float sum = 0.f;
    #pragma unroll
    for (int i = 0; i < 6; i++) { v[i] = expf(v[i] - m); sum += v[i]; }
    #pragma unroll
    for (int o = 16; o; o >>= 1) sum += __shfl_xor_sync(0xffffffffu, sum, o);
    const float inv = 1.f / sum;
    #pragma unroll
    for (int i = 0; i < 6; i++)
        s[lane + 32*i] = __uint_as_float(f2tf32(v[i] * inv));
}

// ---------------------------------------------------------------------------
// K5/K6: attention apply on tf32 mma (R5 layout: grid (4, line, b), 2 CTA/SM)
// ---------------------------------------------------------------------------
#define AT_AP 100
#define AT_BP 136
#define AT_SMEM ((96*AT_AP + 96*AT_BP)*4)   // 90624

__global__ __launch_bounds__(256) void yv_mma() {
    extern __shared__ float sm[];
    float* As = sm;
    float* Bs = sm + 96*AT_AP;
    const uint32_t sbase = smem_u32(sm);
    const int b = blockIdx.z, w = blockIdx.y, c0 = blockIdx.x * 128;
    const int tid = threadIdx.x;
    const int wid = tid >> 5, lane = tid & 31;
    const int gid = lane >> 2, tg = lane & 3;
    const int wm = wid >> 2, wn = wid & 3;

    for (int i = tid; i < 96*24; i += 256) {
        int h = i / 24, c4 = i % 24;
        cpasync16(sbase + (uint32_t)(h*AT_AP + c4*4)*4u,
                  &g_S[((size_t)((b*HH + h)*WW) + w)*LL + c4*4]);
    }
    for (int i = tid; i < 96*32; i += 256) {
        int g = i >> 5, c4 = i & 31;
        cpasync16(sbase + (uint32_t)(96*AT_AP + g*AT_BP + c4*4)*4u,
                  &g_v[((size_t)((b*HH + g)*WW) + w)*CCH + c0 + c4*4]);
    }
    CP_COMMIT(); CP_WAIT(0);
    __syncthreads();

    float acc[3][4][4];
    #pragma unroll
    for (int mt = 0; mt < 3; mt++)
        #pragma unroll
        for (int nt = 0; nt < 4; nt++)
            #pragma unroll
            for (int i = 0; i < 4; i++) acc[mt][nt][i] = 0.f;

    #pragma unroll
    for (int ks = 0; ks < 12; ks++) {
        const int k0 = ks * 8;
        uint32_t a[3][4];
        #pragma unroll
        for (int mt = 0; mt < 3; mt++) {
            const int m = wm * 48 + mt * 16;
            a[mt][0] = __float_as_uint(As[(m + gid)     * AT_AP + k0 + tg]);
            a[mt][1] = __float_as_uint(As[(m + 8 + gid) * AT_AP + k0 + tg]);
            a[mt][2] = __float_as_uint(As[(m + gid)     * AT_AP + k0 + tg + 4]);
            a[mt][3] = __float_as_uint(As[(m + 8 + gid) * AT_AP + k0 + tg + 4]);
        }
        uint32_t bf[4][2];
        #pragma unroll
        for (int nt = 0; nt < 4; nt++) {
            const int col = wn * 32 + nt * 8 + gid;
            bf[nt][0] = __float_as_uint(Bs[(k0 + tg)     * AT_BP + col]);
            bf[nt][1] = __float_as_uint(Bs[(k0 + tg + 4) * AT_BP + col]);
        }
        #pragma unroll
        for (int mt = 0; mt < 3; mt++)
            #pragma unroll
            for (int nt = 0; nt < 4; nt++)
                mma_tf32(acc[mt][nt][0], acc[mt][nt][1], acc[mt][nt][2], acc[mt][nt][3],
                         a[mt][0], a[mt][1], a[mt][2], a[mt][3],
                         bf[nt][0], bf[nt][1]);
    }

    #pragma unroll
    for (int mt = 0; mt < 3; mt++) {
        const int row0 = wm * 48 + mt * 16 + gid;
        #pragma unroll
        for (int nt = 0; nt < 4; nt++) {
            const int col = c0 + wn * 32 + nt * 8 + tg * 2;
            size_t o0 = ((size_t)((b*HH + row0)*WW) + w)*CCH + col;
            size_t o1 = ((size_t)((b*HH + row0 + 8)*WW) + w)*CCH + col;
            *reinterpret_cast<float2*>(&g_yv[o0]) = make_float2(acc[mt][nt][0], acc[mt][nt][1]);
            *reinterpret_cast<float2*>(&g_yv[o1]) = make_float2(acc[mt][nt][2], acc[mt][nt][3]);
        }
    }
}

__global__ __launch_bounds__(256) void yh_mma(
    const float* __restrict__ x, const float* __restrict__ gamma,
    float* __restrict__ out)
{
    extern __shared__ float sm[];
    float* As = sm;
    float* Bs = sm + 96*AT_AP;
    const uint32_t sbase = smem_u32(sm);
    const int b = blockIdx.z, h = blockIdx.y, c0 = blockIdx.x * 128;
    const int tid = threadIdx.x;
    const int wid = tid >> 5, lane = tid & 31;
    const int gid = lane >> 2, tg = lane & 3;
    const int wm = wid >> 2, wn = wid & 3;
    const size_t rowbase = (size_t)(b*HH + h)*WW;

    for (int i = tid; i < 96*24; i += 256) {
        int r = i / 24, c4 = i % 24;
        cpasync16(sbase + (uint32_t)(r*AT_AP + c4*4)*4u,
                  &g_S[(rowbase + r)*LL + 96 + c4*4]);
    }
    for (int i = tid; i < 96*32; i += 256) {
        int u = i >> 5, c4 = i & 31;
        cpasync16(sbase + (uint32_t)(96*AT_AP + u*AT_BP + c4*4)*4u,
                  &g_v[(rowbase + u)*CCH + c0 + c4*4]);
    }
    CP_COMMIT(); CP_WAIT(0);
    __syncthreads();

    float acc[3][4][4];
    #pragma unroll
    for (int mt = 0; mt < 3; mt++)
        #pragma unroll
        for (int nt = 0; nt < 4; nt++)
            #pragma unroll
            for (int i = 0; i < 4; i++) acc[mt][nt][i] = 0.f;

    #pragma unroll
    for (int ks = 0; ks < 12; ks++) {
        const int k0 = ks * 8;
        uint32_t a[3][4];
        #pragma unroll
        for (int mt = 0; mt < 3; mt++) {
            const int m = wm * 48 + mt * 16;
            a[mt][0] = __float_as_uint(As[(m + gid)     * AT_AP + k0 + tg]);
            a[mt][1] = __float_as_uint(As[(m + 8 + gid) * AT_AP + k0 + tg]);
            a[mt][2] = __float_as_uint(As[(m + gid)     * AT_AP + k0 + tg + 4]);
            a[mt][3] = __float_as_uint(As[(m + 8 + gid) * AT_AP + k0 + tg + 4]);
        }
        uint32_t bf[4][2];
        #pragma unroll
        for (int nt = 0; nt < 4; nt++) {
            const int col = wn * 32 + nt * 8 + gid;
            bf[nt][0] = __float_as_uint(Bs[(k0 + tg)     * AT_BP + col]);
            bf[nt][1] = __float_as_uint(Bs[(k0 + tg + 4) * AT_BP + col]);
        }
        #pragma unroll
        for (int mt = 0; mt < 3; mt++)
            #pragma unroll
            for (int nt = 0; nt < 4; nt++)
                mma_tf32(acc[mt][nt][0], acc[mt][nt][1], acc[mt][nt][2], acc[mt][nt][3],
                         a[mt][0], a[mt][1], a[mt][2], a[mt][3],
                         bf[nt][0], bf[nt][1]);
    }

    const float gm = *gamma;
    #pragma unroll
    for (int mt = 0; mt < 3; mt++) {
        const int row0 = wm * 48 + mt * 16 + gid;
        #pragma unroll
        for (int nt = 0; nt < 4; nt++) {
            const int col = c0 + wn * 32 + nt * 8 + tg * 2;
            size_t o0 = (rowbase + row0)*CCH + col;
            size_t o1 = (rowbase + row0 + 8)*CCH + col;
            float2 yv0 = *reinterpret_cast<const float2*>(&g_yv[o0]);
            float2 yv1 = *reinterpret_cast<const float2*>(&g_yv[o1]);
            float2 x0  = *reinterpret_cast<const float2*>(&x[o0]);
            float2 x1  = *reinterpret_cast<const float2*>(&x[o1]);
            float2 r0, r1;
            r0.x = fmaf(acc[mt][nt][0] + yv0.x, gm, x0.x);
            r0.y = fmaf(acc[mt][nt][1] + yv0.y, gm, x0.y);
            r1.x = fmaf(acc[mt][nt][2] + yv1.x, gm, x1.x);
            r1.y = fmaf(acc[mt][nt][3] + yv1.y, gm, x1.y);
            *reinterpret_cast<float2*>(&out[o0]) = r0;
            *reinterpret_cast<float2*>(&out[o1]) = r1;
        }
    }
}

// ---------------------------------------------------------------------------
extern "C" void kernel_launch(void* const* d_in, const int* in_sizes, int n_in,
                              void* d_out, int out_size)
{
    const float* x     = (const float*)d_in[0];
    const float* Wq    = (const float*)d_in[1];
    const float* bq    = (const float*)d_in[2];
    const float* Wk    = (const float*)d_in[3];
    const float* bk    = (const float*)d_in[4];
    const float* Wv    = (const float*)d_in[5];
    const float* bv    = (const float*)d_in[6];
    const float* gamma = (const float*)d_in[7];
    float* out = (float*)d_out;

    float *qkp, *vp, *xt, *wvt, *wqkt, *bqk;
    cudaGetSymbolAddress((void**)&qkp,  g_qk);
    cudaGetSymbolAddress((void**)&vp,   g_v);
    cudaGetSymbolAddress((void**)&xt,   g_xt);
    cudaGetSymbolAddress((void**)&wvt,  g_wvt);
    cudaGetSymbolAddress((void**)&wqkt, g_wqkt);
    cudaGetSymbolAddress((void**)&bqk,  g_bqk);

    cudaFuncSetAttribute(proj_mma,         cudaFuncAttributeMaxDynamicSharedMemorySize, P_SMEM);
    cudaFuncSetAttribute(score_mma<true>,  cudaFuncAttributeMaxDynamicSharedMemorySize, SC_SMEM);
    cudaFuncSetAttribute(score_mma<false>, cudaFuncAttributeMaxDynamicSharedMemorySize, SC_SMEM);
    cudaFuncSetAttribute(yv_mma,           cudaFuncAttributeMaxDynamicSharedMemorySize, AT_SMEM);
    cudaFuncSetAttribute(yh_mma,           cudaFuncAttributeMaxDynamicSharedMemorySize, AT_SMEM);

    // Pre-round
    round_tf32_kernel<<<(NPOS*CCH/4 + 255)/256, 256>>>(x,  xt,  (size_t)NPOS*CCH/4);
    round_tf32_kernel<<<(CCH*CCH/4  + 255)/256, 256>>>(Wv, wvt, (size_t)CCH*CCH/4);
    prep_qk_kernel<<<(CCH*128 + 255)/256, 256>>>(Wq, Wk, bq, bk);

    // Projections (outputs tf32-rounded)
    proj_mma<<<dim3(CCH/128, NPOS/128), 256, P_SMEM>>>(xt, wvt,  bv,  vp,  CCH);
    proj_mma<<<dim3(1,       NPOS/128), 256, P_SMEM>>>(xt, wqkt, bqk, qkp, 128);

    // Scores on mma (raw, diag masked in sv)
    score_mma<true> <<<dim3(WW, BB), 256, SC_SMEM>>>();
    score_mma<false><<<dim3(HH, BB), 256, SC_SMEM>>>();

    // Softmax (probs tf32-rounded)
    softmax_kernel<<<NPOS/4, 128>>>();

    // Apply (R5 layout: 4 col-chunks per launch axis, 2 CTA/SM)
    yv_mma<<<dim3(4, WW, BB), 256, AT_SMEM>>>();
    yh_mma<<<dim3(4, HH, BB), 256, AT_SMEM>>>(x, gamma, out);
}

// round 8
// speedup vs baseline: 1.2837x; 1.0100x over previous
#include <cuda_runtime.h>
#include <math.h>
#include <stdint.h>

// Problem dims
#define BB   8
#define HH   96
#define WW   96
#define CCH  512
#define DD   64
#define LL   192
#define NPOS (BB*HH*WW)   // 73728

// ---------------------------------------------------------------------------
// Scratch (device globals)
// ---------------------------------------------------------------------------
__device__ float g_qk[(size_t)NPOS*128];    // q | k packed, tf32-rounded
__device__ float g_v [(size_t)NPOS*CCH];    // tf32-rounded
__device__ float g_S [(size_t)NPOS*LL];     // scores -> probs (in place)
__device__ float g_yv[(size_t)NPOS*CCH];
__device__ float g_xt[(size_t)NPOS*CCH];    // tf32-rounded x
__device__ float g_wvt [(size_t)CCH*CCH];   // Wv^T  [M=512][K=512], tf32-rounded
__device__ float g_wqkt[(size_t)128*CCH];   // [Wq|Wk]^T [128][512], tf32-rounded
__device__ float g_bqk [128];

// ---------------------------------------------------------------------------
// Helpers (baseline PTX, sm_80+)
// ---------------------------------------------------------------------------
__device__ __forceinline__ uint32_t smem_u32(const void* p) {
    uint32_t a;
    asm("{ .reg .u64 t; cvta.to.shared.u64 t, %1; cvt.u32.u64 %0, t; }" : "=r"(a) : "l"(p));
    return a;
}
__device__ __forceinline__ uint32_t f2tf32(float f) {
    uint32_t r;
    asm("cvt.rna.tf32.f32 %0, %1;" : "=r"(r) : "f"(f));
    return r;
}
__device__ __forceinline__ void mma_tf32(
    float& c0, float& c1, float& c2, float& c3,
    uint32_t a0, uint32_t a1, uint32_t a2, uint32_t a3,
    uint32_t b0, uint32_t b1)
{
    asm volatile(
        "mma.sync.aligned.m16n8k8.row.col.f32.tf32.tf32.f32 "
        "{%0,%1,%2,%3}, {%4,%5,%6,%7}, {%8,%9}, {%0,%1,%2,%3};"
        : "+f"(c0), "+f"(c1), "+f"(c2), "+f"(c3)
        : "r"(a0), "r"(a1), "r"(a2), "r"(a3), "r"(b0), "r"(b1));
}
__device__ __forceinline__ void ldsm4(uint32_t& r0, uint32_t& r1, uint32_t& r2, uint32_t& r3, uint32_t a) {
    asm volatile("ldmatrix.sync.aligned.m8n8.x4.shared.b16 {%0,%1,%2,%3}, [%4];"
        : "=r"(r0), "=r"(r1), "=r"(r2), "=r"(r3) : "r"(a));
}
__device__ __forceinline__ void ldsm2(uint32_t& r0, uint32_t& r1, uint32_t a) {
    asm volatile("ldmatrix.sync.aligned.m8n8.x2.shared.b16 {%0,%1}, [%2];"
        : "=r"(r0), "=r"(r1) : "r"(a));
}
__device__ __forceinline__ void cpasync16(uint32_t dst, const void* src) {
    asm volatile("cp.async.cg.shared.global [%0], [%1], 16;" :: "r"(dst), "l"(src));
}
#define CP_COMMIT() asm volatile("cp.async.commit_group;" ::: "memory")
#define CP_WAIT(n)  asm volatile("cp.async.wait_group %0;" :: "n"(n) : "memory")

// ---------------------------------------------------------------------------
// P0: tf32 pre-round (x)
// ---------------------------------------------------------------------------
__global__ __launch_bounds__(256) void round_tf32_kernel(
    const float* __restrict__ src, float* __restrict__ dst, size_t n4)
{
    size_t i = (size_t)blockIdx.x * 256 + threadIdx.x;
    if (i >= n4) return;
    float4 v = *reinterpret_cast<const float4*>(src + i * 4);
    float4 o;
    o.x = __uint_as_float(f2tf32(v.x));
    o.y = __uint_as_float(f2tf32(v.y));
    o.z = __uint_as_float(f2tf32(v.z));
    o.w = __uint_as_float(f2tf32(v.w));
    *reinterpret_cast<float4*>(dst + i * 4) = o;
}

// P1: transpose + round Wv: Wt[m][k] = rnd(W[k*M + m]),  M=512
__global__ __launch_bounds__(256) void prep_wv_kernel(const float* __restrict__ W) {
    int idx = blockIdx.x * 256 + threadIdx.x;
    if (idx >= CCH * CCH) return;
    int m = idx >> 9, k = idx & 511;
    g_wvt[idx] = __uint_as_float(f2tf32(W[(size_t)k * CCH + m]));
}

// P2: build transposed rounded [Wq|Wk]^T [128][512] and bias
__global__ __launch_bounds__(256) void prep_qk_kernel(
    const float* __restrict__ Wq, const float* __restrict__ Wk,
    const float* __restrict__ bq, const float* __restrict__ bk)
{
    int idx = blockIdx.x * 256 + threadIdx.x;
    if (idx < 128 * CCH) {
        int j = idx >> 9, k = idx & 511;
        float v = (j < 64) ? Wq[(size_t)k * 64 + j] : Wk[(size_t)k * 64 + (j - 64)];
        g_wqkt[idx] = __uint_as_float(f2tf32(v));
    }
    if (blockIdx.x == 0 && threadIdx.x < 128) {
        int j = threadIdx.x;
        g_bqk[j] = (j < 64) ? bq[j] : bk[j - 64];
    }
}

// ---------------------------------------------------------------------------
// K1: tf32 projection GEMM, ldmatrix operand feed.
//   C[r, n0+c] = sum_k X[r,k] * Wt[n0+c, k] + bias[c]
//   BM=BN=128, BK=32. A tile [128][36], B tile [128][36] (both k-contig rows).
//   8 warps (2m x 4n), warp tile 64x32. Double-buffered cp.async.
// ---------------------------------------------------------------------------
#define PJ_P 36
#define PJ_TSZ (128*PJ_P)
#define P_SMEM (2*2*PJ_TSZ*4)   // 2 stages x (A+B) = 73728 B

__global__ __launch_bounds__(256) void proj_mma(
    const float* __restrict__ X, const float* __restrict__ Wt,
    const float* __restrict__ bias, float* __restrict__ C, int M)
{
    constexpr int BK = 32, NCH = CCH / BK;
    extern __shared__ float sm[];
    const uint32_t sbase = smem_u32(sm);
    const int tid = threadIdx.x;
    const int wid = tid >> 5, lane = tid & 31;
    const int gid = lane >> 2, tg = lane & 3;
    const int wm = wid >> 2, wn = wid & 3;
    const int rowBase = blockIdx.y * 128;
    const int n0 = blockIdx.x * 128;

    // ldmatrix lane-derived offsets (in floats)
    const int a_row = (lane & 15), a_k = (lane >> 4) * 4;          // A and any k-contig operand
    const int b_row = ((lane >> 4) * 8) + (lane & 7);              // within a 16-row pair
    const int b_k   = ((lane >> 3) & 1) * 4;

    float acc[4][4][4];
    #pragma unroll
    for (int mt = 0; mt < 4; mt++)
        #pragma unroll
        for (int nt = 0; nt < 4; nt++)
            #pragma unroll
            for (int i = 0; i < 4; i++) acc[mt][nt][i] = 0.f;

    auto issue = [&](int ch, int buf) {
        const int kc = ch * BK;
        const uint32_t abase = sbase + (uint32_t)(buf * 2 * PJ_TSZ) * 4u;
        const uint32_t bbase = abase + (uint32_t)PJ_TSZ * 4u;
        #pragma unroll
        for (int i = 0; i < 4; i++) {
            int idx = tid + i * 256;
            int r = idx >> 3, c4 = idx & 7;
            cpasync16(abase + (uint32_t)(r * PJ_P + c4 * 4) * 4u,
                      &X[(size_t)(rowBase + r) * CCH + kc + c4 * 4]);
            cpasync16(bbase + (uint32_t)(r * PJ_P + c4 * 4) * 4u,
                      &Wt[(size_t)(n0 + r) * CCH + kc + c4 * 4]);
        }
        CP_COMMIT();
    };

    issue(0, 0);
    for (int ch = 0; ch < NCH; ch++) {
        const int buf = ch & 1;
        if (ch + 1 < NCH) { issue(ch + 1, buf ^ 1); CP_WAIT(1); }
        else              { CP_WAIT(0); }
        __syncthreads();

        const uint32_t Ab = sbase + (uint32_t)(buf * 2 * PJ_TSZ) * 4u;
        const uint32_t Bb = Ab + (uint32_t)PJ_TSZ * 4u;
        #pragma unroll
        for (int ks = 0; ks < 4; ks++) {
            const int k0 = ks * 8;
            uint32_t a[4][4];
            #pragma unroll
            for (int mt = 0; mt < 4; mt++) {
                ldsm4(a[mt][0], a[mt][1], a[mt][2], a[mt][3],
                      Ab + (uint32_t)((wm*64 + mt*16 + a_row) * PJ_P + k0 + a_k) * 4u);
            }
            uint32_t b[4][2];
            #pragma unroll
            for (int pr = 0; pr < 2; pr++) {
                ldsm4(b[pr*2][0], b[pr*2][1], b[pr*2+1][0], b[pr*2+1][1],
                      Bb + (uint32_t)((wn*32 + pr*16 + b_row) * PJ_P + k0 + b_k) * 4u);
            }
            #pragma unroll
            for (int mt = 0; mt < 4; mt++)
                #pragma unroll
                for (int nt = 0; nt < 4; nt++)
                    mma_tf32(acc[mt][nt][0], acc[mt][nt][1], acc[mt][nt][2], acc[mt][nt][3],
                             a[mt][0], a[mt][1], a[mt][2], a[mt][3],
                             b[nt][0], b[nt][1]);
        }
        __syncthreads();
    }

    #pragma unroll
    for (int mt = 0; mt < 4; mt++) {
        const int row = rowBase + wm * 64 + mt * 16 + gid;
        #pragma unroll
        for (int nt = 0; nt < 4; nt++) {
            const int col = n0 + wn * 32 + nt * 8 + tg * 2;
            const float b0 = bias[col], b1 = bias[col + 1];
            C[(size_t)row * M + col]           = __uint_as_float(f2tf32(acc[mt][nt][0] + b0));
            C[(size_t)row * M + col + 1]       = __uint_as_float(f2tf32(acc[mt][nt][1] + b1));
            C[(size_t)(row + 8) * M + col]     = __uint_as_float(f2tf32(acc[mt][nt][2] + b0));
            C[(size_t)(row + 8) * M + col + 1] = __uint_as_float(f2tf32(acc[mt][nt][3] + b1));
        }
    }
}

// ---------------------------------------------------------------------------
// K2/K3: score GEMMs, ldmatrix feed on both operands.
//   sv: block (w,b), rows=h, cols=g, diag masked.  sh: block (h,b), rows=w, cols=u.
// ---------------------------------------------------------------------------
#define SC_P 68
#define SC_SMEM (2*96*SC_P*4)    // 52224

template<bool SV>
__global__ __launch_bounds__(256) void score_mma() {
    extern __shared__ float sm[];
    const uint32_t sbase = smem_u32(sm);
    const uint32_t Qb = sbase;
    const uint32_t Kb = sbase + (uint32_t)(96*SC_P)*4u;
    const int b = blockIdx.y, line = blockIdx.x;
    const int tid = threadIdx.x;
    const int wid = tid >> 5, lane = tid & 31;
    const int gid = lane >> 2, tg = lane & 3;
    const int wm = wid >> 2, wn = wid & 3;

    const int a_row = (lane & 15), a_k = (lane >> 4) * 4;
    const int b_row = ((lane >> 4) * 8) + (lane & 7);
    const int b_k   = ((lane >> 3) & 1) * 4;
    const int b2_row = (lane & 7);                         // x2 variant (lanes 0-15)
    const int b2_k   = ((lane >> 3) & 1) * 4;

    for (int i = tid; i < 96*16; i += 256) {
        int r = i >> 4, c4 = i & 15;
        size_t src = SV
            ? ((size_t)((b*HH + r)*WW) + line)*128
            : ((size_t)((b*HH + line)*WW) + r)*128;
        cpasync16(Qb + (uint32_t)(r*SC_P + c4*4)*4u, &g_qk[src + c4*4]);
        cpasync16(Kb + (uint32_t)(r*SC_P + c4*4)*4u, &g_qk[src + 64 + c4*4]);
    }
    CP_COMMIT(); CP_WAIT(0);
    __syncthreads();

    float acc[3][3][4];
    #pragma unroll
    for (int mt = 0; mt < 3; mt++)
        #pragma unroll
        for (int nt = 0; nt < 3; nt++)
            #pragma unroll
            for (int i = 0; i < 4; i++) acc[mt][nt][i] = 0.f;

    #pragma unroll
    for (int ks = 0; ks < 8; ks++) {
        const int k0 = ks * 8;
        uint32_t a[3][4];
        #pragma unroll
        for (int mt = 0; mt < 3; mt++)
            ldsm4(a[mt][0], a[mt][1], a[mt][2], a[mt][3],
                  Qb + (uint32_t)((wm*48 + mt*16 + a_row) * SC_P + k0 + a_k) * 4u);
        uint32_t bf[3][2];
        ldsm4(bf[0][0], bf[0][1], bf[1][0], bf[1][1],
              Kb + (uint32_t)((wn*24 + b_row) * SC_P + k0 + b_k) * 4u);
        ldsm2(bf[2][0], bf[2][1],
              Kb + (uint32_t)((wn*24 + 16 + b2_row) * SC_P + k0 + b2_k) * 4u);
        #pragma unroll
        for (int mt = 0; mt < 3; mt++)
            #pragma unroll
            for (int nt = 0; nt < 3; nt++)
                mma_tf32(acc[mt][nt][0], acc[mt][nt][1], acc[mt][nt][2], acc[mt][nt][3],
                         a[mt][0], a[mt][1], a[mt][2], a[mt][3],
                         bf[nt][0], bf[nt][1]);
    }

    #pragma unroll
    for (int mt = 0; mt < 3; mt++) {
        const int r0 = wm * 48 + mt * 16 + gid;
        #pragma unroll
        for (int nt = 0; nt < 3; nt++) {
            const int c0 = wn * 24 + nt * 8 + tg * 2;
            #pragma unroll
            for (int half = 0; half < 2; half++) {
                const int r = r0 + half * 8;
                size_t base = SV
                    ? ((size_t)((b*HH + r)*WW) + line)*LL
                    : ((size_t)((b*HH + line)*WW) + r)*LL + 96;
                float v0 = acc[mt][nt][half*2],  v1 = acc[mt][nt][half*2 + 1];
                if (SV) {
                    if (c0     == r) v0 = -1e30f;
                    if (c0 + 1 == r) v1 = -1e30f;
                }
                g_S[base + c0]     = v0;
                g_S[base + c0 + 1] = v1;
            }
        }
    }
}

// ---------------------------------------------------------------------------
// K4: softmax over 192, in place; writes tf32-rounded probs.
// ---------------------------------------------------------------------------
__global__ __launch_bounds__(128) void softmax_kernel() {
    const int lane = threadIdx.x & 31;
    const size_t pos = (size_t)blockIdx.x * 4 + (threadIdx.x >> 5);
    float* s = g_S + pos * LL;
    float v[6];
    float m = -3.4e38f;
    #pragma unroll
    for (int i = 0; i < 6; i++) { v[i] = s[lane + 32*i]; m = fmaxf(m, v[i]); }
    #pragma unroll
    for (int o = 16; o; o >>= 1) m = fmaxf(m, __shfl_xor_sync(0xffffffffu, m, o));
    float sum = 0.f;
    #pragma unroll
    for (int i = 0; i < 6; i++) { v[i] = expf(v[i] - m); sum += v[i]; }
    #pragma unroll
    for (int o = 16; o; o >>= 1) sum += __shfl_xor_sync(0xffffffffu, sum, o);
    const float inv = 1.f / sum;
    #pragma unroll
    for (int i = 0; i < 6; i++)
        s[lane + 32*i] = __uint_as_float(f2tf32(v[i] * inv));
}

// ---------------------------------------------------------------------------
// K5/K6: attention apply. A-probs via ldmatrix; V via scalar LDS (k-major need).
// ---------------------------------------------------------------------------
#define AT_AP 100
#define AT_BP 136
#define AT_SMEM ((96*AT_AP + 96*AT_BP)*4)   // 90624

__global__ __launch_bounds__(256) void yv_mma() {
    extern __shared__ float sm[];
    float* Bs = sm + 96*AT_AP;
    const uint32_t sbase = smem_u32(sm);
    const int b = blockIdx.z, w = blockIdx.y, c0 = blockIdx.x * 128;
    const int tid = threadIdx.x;
    const int wid = tid >> 5, lane = tid & 31;
    const int gid = lane >> 2, tg = lane & 3;
    const int wm = wid >> 2, wn = wid & 3;
    const int a_row = (lane & 15), a_k = (lane >> 4) * 4;

    for (int i = tid; i < 96*24; i += 256) {
        int h = i / 24, c4 = i % 24;
        cpasync16(sbase + (uint32_t)(h*AT_AP + c4*4)*4u,
                  &g_S[((size_t)((b*HH + h)*WW) + w)*LL + c4*4]);
    }
    for (int i = tid; i < 96*32; i += 256) {
        int g = i >> 5, c4 = i & 31;
        cpasync16(sbase + (uint32_t)(96*AT_AP + g*AT_BP + c4*4)*4u,
                  &g_v[((size_t)((b*HH + g)*WW) + w)*CCH + c0 + c4*4]);
    }
    CP_COMMIT(); CP_WAIT(0);
    __syncthreads();

    float acc[3][4][4];
    #pragma unroll
    for (int mt = 0; mt < 3; mt++)
        #pragma unroll
        for (int nt = 0; nt < 4; nt++)
            #pragma unroll
            for (int i = 0; i < 4; i++) acc[mt][nt][i] = 0.f;

    #pragma unroll
    for (int ks = 0; ks < 12; ks++) {
        const int k0 = ks * 8;
        uint32_t a[3][4];
        #pragma unroll
        for (int mt = 0; mt < 3; mt++)
            ldsm4(a[mt][0], a[mt][1], a[mt][2], a[mt][3],
                  sbase + (uint32_t)((wm*48 + mt*16 + a_row) * AT_AP + k0 + a_k) * 4u);
        uint32_t bf[4][2];
        #pragma unroll
        for (int nt = 0; nt < 4; nt++) {
            const int col = wn * 32 + nt * 8 + gid;
            bf[nt][0] = __float_as_uint(Bs[(k0 + tg)     * AT_BP + col]);
            bf[nt][1] = __float_as_uint(Bs[(k0 + tg + 4) * AT_BP + col]);
        }
        #pragma unroll
        for (int mt = 0; mt < 3; mt++)
            #pragma unroll
            for (int nt = 0; nt < 4; nt++)
                mma_tf32(acc[mt][nt][0], acc[mt][nt][1], acc[mt][nt][2], acc[mt][nt][3],
                         a[mt][0], a[mt][1], a[mt][2], a[mt][3],
                         bf[nt][0], bf[nt][1]);
    }

    #pragma unroll
    for (int mt = 0; mt < 3; mt++) {
        const int row0 = wm * 48 + mt * 16 + gid;
        #pragma unroll
        for (int nt = 0; nt < 4; nt++) {
            const int col = c0 + wn * 32 + nt * 8 + tg * 2;
            size_t o0 = ((size_t)((b*HH + row0)*WW) + w)*CCH + col;
            size_t o1 = ((size_t)((b*HH + row0 + 8)*WW) + w)*CCH + col;
            *reinterpret_cast<float2*>(&g_yv[o0]) = make_float2(acc[mt][nt][0], acc[mt][nt][1]);
            *reinterpret_cast<float2*>(&g_yv[o1]) = make_float2(acc[mt][nt][2], acc[mt][nt][3]);
        }
    }
}

__global__ __launch_bounds__(256) void yh_mma(
    const float* __restrict__ x, const float* __restrict__ gamma,
    float* __restrict__ out)
{
    extern __shared__ float sm[];
    float* Bs = sm + 96*AT_AP;
    const uint32_t sbase = smem_u32(sm);
    const int b = blockIdx.z, h = blockIdx.y, c0 = blockIdx.x * 128;
    const int tid = threadIdx.x;
    const int wid = tid >> 5, lane = tid & 31;
    const int gid = lane >> 2, tg = lane & 3;
    const int wm = wid >> 2, wn = wid & 3;
    const int a_row = (lane & 15), a_k = (lane >> 4) * 4;
    const size_t rowbase = (size_t)(b*HH + h)*WW;

    for (int i = tid; i < 96*24; i += 256) {
        int r = i / 24, c4 = i % 24;
        cpasync16(sbase + (uint32_t)(r*AT_AP + c4*4)*4u,
                  &g_S[(rowbase + r)*LL + 96 + c4*4]);
    }
    for (int i = tid; i < 96*32; i += 256) {
        int u = i >> 5, c4 = i & 31;
        cpasync16(sbase + (uint32_t)(96*AT_AP + u*AT_BP + c4*4)*4u,
                  &g_v[(rowbase + u)*CCH + c0 + c4*4]);
    }
    CP_COMMIT(); CP_WAIT(0);
    __syncthreads();

    float acc[3][4][4];
    #pragma unroll
    for (int mt = 0; mt < 3; mt++)
        #pragma unroll
        for (int nt = 0; nt < 4; nt++)
            #pragma unroll
            for (int i = 0; i < 4; i++) acc[mt][nt][i] = 0.f;

    #pragma unroll
    for (int ks = 0; ks < 12; ks++) {
        const int k0 = ks * 8;
        uint32_t a[3][4];
        #pragma unroll
        for (int mt = 0; mt < 3; mt++)
            ldsm4(a[mt][0], a[mt][1], a[mt][2], a[mt][3],
                  sbase + (uint32_t)((wm*48 + mt*16 + a_row) * AT_AP + k0 + a_k) * 4u);
        uint32_t bf[4][2];
        #pragma unroll
        for (int nt = 0; nt < 4; nt++) {
            const int col = wn * 32 + nt * 8 + gid;
            bf[nt][0] = __float_as_uint(Bs[(k0 + tg)     * AT_BP + col]);
            bf[nt][1] = __float_as_uint(Bs[(k0 + tg + 4) * AT_BP + col]);
        }
        #pragma unroll
        for (int mt = 0; mt < 3; mt++)
            #pragma unroll
            for (int nt = 0; nt < 4; nt++)
                mma_tf32(acc[mt][nt][0], acc[mt][nt][1], acc[mt][nt][2], acc[mt][nt][3],
                         a[mt][0], a[mt][1], a[mt][2], a[mt][3],
                         bf[nt][0], bf[nt][1]);
    }

    const float gm = *gamma;
    #pragma unroll
    for (int mt = 0; mt < 3; mt++) {
        const int row0 = wm * 48 + mt * 16 + gid;
        #pragma unroll
        for (int nt = 0; nt < 4; nt++) {
            const int col = c0 + wn * 32 + nt * 8 + tg * 2;
            size_t o0 = (rowbase + row0)*CCH + col;
            size_t o1 = (rowbase + row0 + 8)*CCH + col;
            float2 yv0 = *reinterpret_cast<const float2*>(&g_yv[o0]);
            float2 yv1 = *reinterpret_cast<const float2*>(&g_yv[o1]);
            float2 x0  = *reinterpret_cast<const float2*>(&x[o0]);
            float2 x1  = *reinterpret_cast<const float2*>(&x[o1]);
            float2 r0, r1;
            r0.x = fmaf(acc[mt][nt][0] + yv0.x, gm, x0.x);
            r0.y = fmaf(acc[mt][nt][1] + yv0.y, gm, x0.y);
            r1.x = fmaf(acc[mt][nt][2] + yv1.x, gm, x1.x);
            r1.y = fmaf(acc[mt][nt][3] + yv1.y, gm, x1.y);
            *reinterpret_cast<float2*>(&out[o0]) = r0;
            *reinterpret_cast<float2*>(&out[o1]) = r1;
        }
    }
}

// ---------------------------------------------------------------------------
extern "C" void kernel_launch(void* const* d_in, const int* in_sizes, int n_in,
                              void* d_out, int out_size)
{
    const float* x     = (const float*)d_in[0];
    const float* Wq    = (const float*)d_in[1];
    const float* bq    = (const float*)d_in[2];
    const float* Wk    = (const float*)d_in[3];
    const float* bk    = (const float*)d_in[4];
    const float* Wv    = (const float*)d_in[5];
    const float* bv    = (const float*)d_in[6];
    const float* gamma = (const float*)d_in[7];
    float* out = (float*)d_out;

    float *qkp, *vp, *xt, *wvt, *wqkt, *bqk;
    cudaGetSymbolAddress((void**)&qkp,  g_qk);
    cudaGetSymbolAddress((void**)&vp,   g_v);
    cudaGetSymbolAddress((void**)&xt,   g_xt);
    cudaGetSymbolAddress((void**)&wvt,  g_wvt);
    cudaGetSymbolAddress((void**)&wqkt, g_wqkt);
    cudaGetSymbolAddress((void**)&bqk,  g_bqk);

    cudaFuncSetAttribute(proj_mma,         cudaFuncAttributeMaxDynamicSharedMemorySize, P_SMEM);
    cudaFuncSetAttribute(score_mma<true>,  cudaFuncAttributeMaxDynamicSharedMemorySize, SC_SMEM);
    cudaFuncSetAttribute(score_mma<false>, cudaFuncAttributeMaxDynamicSharedMemorySize, SC_SMEM);
    cudaFuncSetAttribute(yv_mma,           cudaFuncAttributeMaxDynamicSharedMemorySize, AT_SMEM);
    cudaFuncSetAttribute(yh_mma,           cudaFuncAttributeMaxDynamicSharedMemorySize, AT_SMEM);

    // Pre-round + transpose weights
    round_tf32_kernel<<<(NPOS*CCH/4 + 255)/256, 256>>>(x, xt, (size_t)NPOS*CCH/4);
    prep_wv_kernel<<<(CCH*CCH + 255)/256, 256>>>(Wv);
    prep_qk_kernel<<<(128*CCH + 255)/256, 256>>>(Wq, Wk, bq, bk);

    // Projections (outputs tf32-rounded)
    proj_mma<<<dim3(CCH/128, NPOS/128), 256, P_SMEM>>>(xt, wvt,  bv,  vp,  CCH);
    proj_mma<<<dim3(1,       NPOS/128), 256, P_SMEM>>>(xt, wqkt, bqk, qkp, 128);

    // Scores on mma (raw, diag masked in sv)
    score_mma<true> <<<dim3(WW, BB), 256, SC_SMEM>>>();
    score_mma<false><<<dim3(HH, BB), 256, SC_SMEM>>>();

    // Softmax (probs tf32-rounded)
    softmax_kernel<<<NPOS/4, 128>>>();

    // Apply
    yv_mma<<<dim3(4, WW, BB), 256, AT_SMEM>>>();
    yh_mma<<<dim3(4, HH, BB), 256, AT_SMEM>>>(x, gamma, out);
}

// round 14
// speedup vs baseline: 1.3092x; 1.0199x over previous
#include <cuda_runtime.h>
#include <math.h>
#include <stdint.h>

// Problem dims
#define BB   8
#define HH   96
#define WW   96
#define CCH  512
#define DD   64
#define LL   192
#define NPOS (BB*HH*WW)   // 73728

// ---------------------------------------------------------------------------
// Scratch (device globals)
// ---------------------------------------------------------------------------
__device__ float g_qk[(size_t)NPOS*128];    // q | k packed, tf32-rounded
__device__ float g_v [(size_t)NPOS*CCH];    // tf32-rounded
__device__ float g_S [(size_t)NPOS*LL];     // scores -> probs (in place)
__device__ float g_yv[(size_t)NPOS*CCH];
__device__ float g_xt[(size_t)NPOS*CCH];    // tf32-rounded x
__device__ float g_wvt [(size_t)CCH*CCH];   // Wv^T  [M=512][K=512], tf32-rounded
__device__ float g_wqkt[(size_t)128*CCH];   // [Wq|Wk]^T [128][512], tf32-rounded
__device__ float g_bqk [128];

// ---------------------------------------------------------------------------
// Helpers (baseline PTX, sm_80+)
// ---------------------------------------------------------------------------
__device__ __forceinline__ uint32_t smem_u32(const void* p) {
    uint32_t a;
    asm("{ .reg .u64 t; cvta.to.shared.u64 t, %1; cvt.u32.u64 %0, t; }" : "=r"(a) : "l"(p));
    return a;
}
__device__ __forceinline__ uint32_t f2tf32(float f) {
    uint32_t r;
    asm("cvt.rna.tf32.f32 %0, %1;" : "=r"(r) : "f"(f));
    return r;
}
__device__ __forceinline__ void mma_tf32(
    float& c0, float& c1, float& c2, float& c3,
    uint32_t a0, uint32_t a1, uint32_t a2, uint32_t a3,
    uint32_t b0, uint32_t b1)
{
    asm volatile(
        "mma.sync.aligned.m16n8k8.row.col.f32.tf32.tf32.f32 "
        "{%0,%1,%2,%3}, {%4,%5,%6,%7}, {%8,%9}, {%0,%1,%2,%3};"
        : "+f"(c0), "+f"(c1), "+f"(c2), "+f"(c3)
        : "r"(a0), "r"(a1), "r"(a2), "r"(a3), "r"(b0), "r"(b1));
}
__device__ __forceinline__ void ldsm4(uint32_t& r0, uint32_t& r1, uint32_t& r2, uint32_t& r3, uint32_t a) {
    asm volatile("ldmatrix.sync.aligned.m8n8.x4.shared.b16 {%0,%1,%2,%3}, [%4];"
        : "=r"(r0), "=r"(r1), "=r"(r2), "=r"(r3) : "r"(a));
}
__device__ __forceinline__ void ldsm2(uint32_t& r0, uint32_t& r1, uint32_t a) {
    asm volatile("ldmatrix.sync.aligned.m8n8.x2.shared.b16 {%0,%1}, [%2];"
        : "=r"(r0), "=r"(r1) : "r"(a));
}
__device__ __forceinline__ void cpasync16(uint32_t dst, const void* src) {
    asm volatile("cp.async.cg.shared.global [%0], [%1], 16;" :: "r"(dst), "l"(src));
}
#define CP_COMMIT() asm volatile("cp.async.commit_group;" ::: "memory")
#define CP_WAIT(n)  asm volatile("cp.async.wait_group %0;" :: "n"(n) : "memory")

// ---------------------------------------------------------------------------
// P0: tf32 pre-round (x)
// ---------------------------------------------------------------------------
__global__ __launch_bounds__(256) void round_tf32_kernel(
    const float* __restrict__ src, float* __restrict__ dst, size_t n4)
{
    size_t i = (size_t)blockIdx.x * 256 + threadIdx.x;
    if (i >= n4) return;
    float4 v = *reinterpret_cast<const float4*>(src + i * 4);
    float4 o;
    o.x = __uint_as_float(f2tf32(v.x));
    o.y = __uint_as_float(f2tf32(v.y));
    o.z = __uint_as_float(f2tf32(v.z));
    o.w = __uint_as_float(f2tf32(v.w));
    *reinterpret_cast<float4*>(dst + i * 4) = o;
}

// P1: transpose + round Wv: Wt[m][k] = rnd(W[k*M + m]),  M=512
__global__ __launch_bounds__(256) void prep_wv_kernel(const float* __restrict__ W) {
    int idx = blockIdx.x * 256 + threadIdx.x;
    if (idx >= CCH * CCH) return;
    int m = idx >> 9, k = idx & 511;
    g_wvt[idx] = __uint_as_float(f2tf32(W[(size_t)k * CCH + m]));
}

// P2: build transposed rounded [Wq|Wk]^T [128][512] and bias
__global__ __launch_bounds__(256) void prep_qk_kernel(
    const float* __restrict__ Wq, const float* __restrict__ Wk,
    const float* __restrict__ bq, const float* __restrict__ bk)
{
    int idx = blockIdx.x * 256 + threadIdx.x;
    if (idx < 128 * CCH) {
        int j = idx >> 9, k = idx & 511;
        float v = (j < 64) ? Wq[(size_t)k * 64 + j] : Wk[(size_t)k * 64 + (j - 64)];
        g_wqkt[idx] = __uint_as_float(f2tf32(v));
    }
    if (blockIdx.x == 0 && threadIdx.x < 128) {
        int j = threadIdx.x;
        g_bqk[j] = (j < 64) ? bq[j] : bk[j - 64];
    }
}

// ---------------------------------------------------------------------------
// K1: tf32 projection GEMM, ldmatrix feed, 3-stage cp.async pipeline.
//   C[r, n0+c] = sum_k X[r,k] * Wt[n0+c, k] + bias[c]
//   BM=BN=128, BK=32, one __syncthreads per chunk.
// ---------------------------------------------------------------------------
#define PJ_P 36
#define PJ_TSZ (128*PJ_P)
#define PJ_STG (2*PJ_TSZ)          // A+B per stage (floats)
#define P_SMEM (3*PJ_STG*4)        // 110592 B

__global__ __launch_bounds__(256) void proj_mma(
    const float* __restrict__ X, const float* __restrict__ Wt,
    const float* __restrict__ bias, float* __restrict__ C, int M)
{
    constexpr int BK = 32, NCH = CCH / BK;   // 16 chunks
    extern __shared__ float sm[];
    const uint32_t sbase = smem_u32(sm);
    const int tid = threadIdx.x;
    const int wid = tid >> 5, lane = tid & 31;
    const int gid = lane >> 2, tg = lane & 3;
    const int wm = wid >> 2, wn = wid & 3;
    const int rowBase = blockIdx.y * 128;
    const int n0 = blockIdx.x * 128;

    const int a_row = (lane & 15), a_k = (lane >> 4) * 4;
    const int b_row = ((lane >> 4) * 8) + (lane & 7);
    const int b_k   = ((lane >> 3) & 1) * 4;

    float acc[4][4][4];
    #pragma unroll
    for (int mt = 0; mt < 4; mt++)
        #pragma unroll
        for (int nt = 0; nt < 4; nt++)
            #pragma unroll
            for (int i = 0; i < 4; i++) acc[mt][nt][i] = 0.f;

    auto issue = [&](int ch) {
        const int kc = ch * BK;
        const int buf = ch % 3;
        const uint32_t abase = sbase + (uint32_t)(buf * PJ_STG) * 4u;
        const uint32_t bbase = abase + (uint32_t)PJ_TSZ * 4u;
        #pragma unroll
        for (int i = 0; i < 4; i++) {
            int idx = tid + i * 256;
            int r = idx >> 3, c4 = idx & 7;
            cpasync16(abase + (uint32_t)(r * PJ_P + c4 * 4) * 4u,
                      &X[(size_t)(rowBase + r) * CCH + kc + c4 * 4]);
            cpasync16(bbase + (uint32_t)(r * PJ_P + c4 * 4) * 4u,
                      &Wt[(size_t)(n0 + r) * CCH + kc + c4 * 4]);
        }
        CP_COMMIT();
    };

    issue(0);
    issue(1);
    for (int ch = 0; ch < NCH; ch++) {
        if (ch < NCH - 1) { CP_WAIT(1); }
        else              { CP_WAIT(0); }
        __syncthreads();
        if (ch + 2 < NCH) issue(ch + 2);   // safe: all warps past compute(ch-1)

        const int buf = ch % 3;
        const uint32_t Ab = sbase + (uint32_t)(buf * PJ_STG) * 4u;
        const uint32_t Bb = Ab + (uint32_t)PJ_TSZ * 4u;
        #pragma unroll
        for (int ks = 0; ks < 4; ks++) {
            const int k0 = ks * 8;
            uint32_t a[4][4];
            #pragma unroll
            for (int mt = 0; mt < 4; mt++)
                ldsm4(a[mt][0], a[mt][1], a[mt][2], a[mt][3],
                      Ab + (uint32_t)((wm*64 + mt*16 + a_row) * PJ_P + k0 + a_k) * 4u);
            uint32_t b[4][2];
            #pragma unroll
            for (int pr = 0; pr < 2; pr++)
                ldsm4(b[pr*2][0], b[pr*2][1], b[pr*2+1][0], b[pr*2+1][1],
                      Bb + (uint32_t)((wn*32 + pr*16 + b_row) * PJ_P + k0 + b_k) * 4u);
            #pragma unroll
            for (int mt = 0; mt < 4; mt++)
                #pragma unroll
                for (int nt = 0; nt < 4; nt++)
                    mma_tf32(acc[mt][nt][0], acc[mt][nt][1], acc[mt][nt][2], acc[mt][nt][3],
                             a[mt][0], a[mt][1], a[mt][2], a[mt][3],
                             b[nt][0], b[nt][1]);
        }
    }

    #pragma unroll
    for (int mt = 0; mt < 4; mt++) {
        const int row = rowBase + wm * 64 + mt * 16 + gid;
        #pragma unroll
        for (int nt = 0; nt < 4; nt++) {
            const int col = n0 + wn * 32 + nt * 8 + tg * 2;
            const float b0 = bias[col], b1 = bias[col + 1];
            C[(size_t)row * M + col]           = __uint_as_float(f2tf32(acc[mt][nt][0] + b0));
            C[(size_t)row * M + col + 1]       = __uint_as_float(f2tf32(acc[mt][nt][1] + b1));
            C[(size_t)(row + 8) * M + col]     = __uint_as_float(f2tf32(acc[mt][nt][2] + b0));
            C[(size_t)(row + 8) * M + col + 1] = __uint_as_float(f2tf32(acc[mt][nt][3] + b1));
        }
    }
}

// ---------------------------------------------------------------------------
// K2/K3: score GEMMs, ldmatrix feed on both operands.
// ---------------------------------------------------------------------------
#define SC_P 68
#define SC_SMEM (2*96*SC_P*4)    // 52224

template<bool SV>
__global__ __launch_bounds__(256) void score_mma() {
    extern __shared__ float sm[];
    const uint32_t sbase = smem_u32(sm);
    const uint32_t Qb = sbase;
    const uint32_t Kb = sbase + (uint32_t)(96*SC_P)*4u;
    const int b = blockIdx.y, line = blockIdx.x;
    const int tid = threadIdx.x;
    const int wid = tid >> 5, lane = tid & 31;
    const int gid = lane >> 2, tg = lane & 3;
    const int wm = wid >> 2, wn = wid & 3;

    const int a_row = (lane & 15), a_k = (lane >> 4) * 4;
    const int b_row = ((lane >> 4) * 8) + (lane & 7);
    const int b_k   = ((lane >> 3) & 1) * 4;
    const int b2_row = (lane & 7);
    const int b2_k   = ((lane >> 3) & 1) * 4;

    for (int i = tid; i < 96*16; i += 256) {
        int r = i >> 4, c4 = i & 15;
        size_t src = SV
            ? ((size_t)((b*HH + r)*WW) + line)*128
            : ((size_t)((b*HH + line)*WW) + r)*128;
        cpasync16(Qb + (uint32_t)(r*SC_P + c4*4)*4u, &g_qk[src + c4*4]);
        cpasync16(Kb + (uint32_t)(r*SC_P + c4*4)*4u, &g_qk[src + 64 + c4*4]);
    }
    CP_COMMIT(); CP_WAIT(0);
    __syncthreads();

    float acc[3][3][4];
    #pragma unroll
    for (int mt = 0; mt < 3; mt++)
        #pragma unroll
        for (int nt = 0; nt < 3; nt++)
            #pragma unroll
            for (int i = 0; i < 4; i++) acc[mt][nt][i] = 0.f;

    #pragma unroll
    for (int ks = 0; ks < 8; ks++) {
        const int k0 = ks * 8;
        uint32_t a[3][4];
        #pragma unroll
        for (int mt = 0; mt < 3; mt++)
            ldsm4(a[mt][0], a[mt][1], a[mt][2], a[mt][3],
                  Qb + (uint32_t)((wm*48 + mt*16 + a_row) * SC_P + k0 + a_k) * 4u);
        uint32_t bf[3][2];
        ldsm4(bf[0][0], bf[0][1], bf[1][0], bf[1][1],
              Kb + (uint32_t)((wn*24 + b_row) * SC_P + k0 + b_k) * 4u);
        ldsm2(bf[2][0], bf[2][1],
              Kb + (uint32_t)((wn*24 + 16 + b2_row) * SC_P + k0 + b2_k) * 4u);
        #pragma unroll
        for (int mt = 0; mt < 3; mt++)
            #pragma unroll
            for (int nt = 0; nt < 3; nt++)
                mma_tf32(acc[mt][nt][0], acc[mt][nt][1], acc[mt][nt][2], acc[mt][nt][3],
                         a[mt][0], a[mt][1], a[mt][2], a[mt][3],
                         bf[nt][0], bf[nt][1]);
    }

    #pragma unroll
    for (int mt = 0; mt < 3; mt++) {
        const int r0 = wm * 48 + mt * 16 + gid;
        #pragma unroll
        for (int nt = 0; nt < 3; nt++) {
            const int c0 = wn * 24 + nt * 8 + tg * 2;
            #pragma unroll
            for (int half = 0; half < 2; half++) {
                const int r = r0 + half * 8;
                size_t base = SV
                    ? ((size_t)((b*HH + r)*WW) + line)*LL
                    : ((size_t)((b*HH + line)*WW) + r)*LL + 96;
                float v0 = acc[mt][nt][half*2],  v1 = acc[mt][nt][half*2 + 1];
                if (SV) {
                    if (c0     == r) v0 = -1e30f;
                    if (c0 + 1 == r) v1 = -1e30f;
                }
                g_S[base + c0]     = v0;
                g_S[base + c0 + 1] = v1;
            }
        }
    }
}

// ---------------------------------------------------------------------------
// K4: softmax over 192, in place; writes tf32-rounded probs.
// ---------------------------------------------------------------------------
__global__ __launch_bounds__(128) void softmax_kernel() {
    const int lane = threadIdx.x & 31;
    const size_t pos = (size_t)blockIdx.x * 4 + (threadIdx.x >> 5);
    float* s = g_S + pos * LL;
    float v[6];
    float m = -3.4e38f;
    #pragma unroll
    for (int i = 0; i < 6; i++) { v[i] = s[lane + 32*i]; m = fmaxf(m, v[i]); }
    #pragma unroll
    for (int o = 16; o; o >>= 1) m = fmaxf(m, __shfl_xor_sync(0xffffffffu, m, o));
    float sum = 0.f;
    #pragma unroll
    for (int i = 0; i < 6; i++) { v[i] = expf(v[i] - m); sum += v[i]; }
    #pragma unroll
    for (int o = 16; o; o >>= 1) sum += __shfl_xor_sync(0xffffffffu, sum, o);
    const float inv = 1.f / sum;
    #pragma unroll
    for (int i = 0; i < 6; i++)
        s[lane + 32*i] = __uint_as_float(f2tf32(v[i] * inv));
}

// ---------------------------------------------------------------------------
// K5/K6: attention apply. A via ldmatrix; B scalar LDS. Two-group load:
//   group0 = A + B rows 0..47 (covers ks 0..5), group1 = B rows 48..95.
// ---------------------------------------------------------------------------
#define AT_AP 100
#define AT_BP 136
#define AT_SMEM ((96*AT_AP + 96*AT_BP)*4)   // 90624

__global__ __launch_bounds__(256) void yv_mma() {
    extern __shared__ float sm[];
    float* Bs = sm + 96*AT_AP;
    const uint32_t sbase = smem_u32(sm);
    const int b = blockIdx.z, w = blockIdx.y, c0 = blockIdx.x * 128;
    const int tid = threadIdx.x;
    const int wid = tid >> 5, lane = tid & 31;
    const int gid = lane >> 2, tg = lane & 3;
    const int wm = wid >> 2, wn = wid & 3;
    const int a_row = (lane & 15), a_k = (lane >> 4) * 4;

    // group 0: A + B rows 0..47
    for (int i = tid; i < 96*24; i += 256) {
        int h = i / 24, c4 = i % 24;
        cpasync16(sbase + (uint32_t)(h*AT_AP + c4*4)*4u,
                  &g_S[((size_t)((b*HH + h)*WW) + w)*LL + c4*4]);
    }
    for (int i = tid; i < 48*32; i += 256) {
        int g = i >> 5, c4 = i & 31;
        cpasync16(sbase + (uint32_t)(96*AT_AP + g*AT_BP + c4*4)*4u,
                  &g_v[((size_t)((b*HH + g)*WW) + w)*CCH + c0 + c4*4]);
    }
    CP_COMMIT();
    // group 1: B rows 48..95
    for (int i = tid; i < 48*32; i += 256) {
        int g = (i >> 5) + 48, c4 = i & 31;
        cpasync16(sbase + (uint32_t)(96*AT_AP + g*AT_BP + c4*4)*4u,
                  &g_v[((size_t)((b*HH + g)*WW) + w)*CCH + c0 + c4*4]);
    }
    CP_COMMIT();

    float acc[3][4][4];
    #pragma unroll
    for (int mt = 0; mt < 3; mt++)
        #pragma unroll
        for (int nt = 0; nt < 4; nt++)
            #pragma unroll
            for (int i = 0; i < 4; i++) acc[mt][nt][i] = 0.f;

    CP_WAIT(1);
    __syncthreads();
    #pragma unroll
    for (int phase = 0; phase < 2; phase++) {
        if (phase == 1) { CP_WAIT(0); __syncthreads(); }
        #pragma unroll
        for (int ks6 = 0; ks6 < 6; ks6++) {
            const int ks = phase * 6 + ks6;
            const int k0 = ks * 8;
            uint32_t a[3][4];
            #pragma unroll
            for (int mt = 0; mt < 3; mt++)
                ldsm4(a[mt][0], a[mt][1], a[mt][2], a[mt][3],
                      sbase + (uint32_t)((wm*48 + mt*16 + a_row) * AT_AP + k0 + a_k) * 4u);
            uint32_t bf[4][2];
            #pragma unroll
            for (int nt = 0; nt < 4; nt++) {
                const int col = wn * 32 + nt * 8 + gid;
                bf[nt][0] = __float_as_uint(Bs[(k0 + tg)     * AT_BP + col]);
                bf[nt][1] = __float_as_uint(Bs[(k0 + tg + 4) * AT_BP + col]);
            }
            #pragma unroll
            for (int mt = 0; mt < 3; mt++)
                #pragma unroll
                for (int nt = 0; nt < 4; nt++)
                    mma_tf32(acc[mt][nt][0], acc[mt][nt][1], acc[mt][nt][2], acc[mt][nt][3],
                             a[mt][0], a[mt][1], a[mt][2], a[mt][3],
                             bf[nt][0], bf[nt][1]);
        }
    }

    #pragma unroll
    for (int mt = 0; mt < 3; mt++) {
        const int row0 = wm * 48 + mt * 16 + gid;
        #pragma unroll
        for (int nt = 0; nt < 4; nt++) {
            const int col = c0 + wn * 32 + nt * 8 + tg * 2;
            size_t o0 = ((size_t)((b*HH + row0)*WW) + w)*CCH + col;
            size_t o1 = ((size_t)((b*HH + row0 + 8)*WW) + w)*CCH + col;
            *reinterpret_cast<float2*>(&g_yv[o0]) = make_float2(acc[mt][nt][0], acc[mt][nt][1]);
            *reinterpret_cast<float2*>(&g_yv[o1]) = make_float2(acc[mt][nt][2], acc[mt][nt][3]);
        }
    }
}

__global__ __launch_bounds__(256) void yh_mma(
    const float* __restrict__ x, const float* __restrict__ gamma,
    float* __restrict__ out)
{
    extern __shared__ float sm[];
    float* Bs = sm + 96*AT_AP;
    const uint32_t sbase = smem_u32(sm);
    const int b = blockIdx.z, h = blockIdx.y, c0 = blockIdx.x * 128;
    const int tid = threadIdx.x;
    const int wid = tid >> 5, lane = tid & 31;
    const int gid = lane >> 2, tg = lane & 3;
    const int wm = wid >> 2, wn = wid & 3;
    const int a_row = (lane & 15), a_k = (lane >> 4) * 4;
    const size_t rowbase = (size_t)(b*HH + h)*WW;

    for (int i = tid; i < 96*24; i += 256) {
        int r = i / 24, c4 = i % 24;
        cpasync16(sbase + (uint32_t)(r*AT_AP + c4*4)*4u,
                  &g_S[(rowbase + r)*LL + 96 + c4*4]);
    }
    for (int i = tid; i < 48*32; i += 256) {
        int u = i >> 5, c4 = i & 31;
        cpasync16(sbase + (uint32_t)(96*AT_AP + u*AT_BP + c4*4)*4u,
                  &g_v[(rowbase + u)*CCH + c0 + c4*4]);
    }
    CP_COMMIT();
    for (int i = tid; i < 48*32; i += 256) {
        int u = (i >> 5) + 48, c4 = i & 31;
        cpasync16(sbase + (uint32_t)(96*AT_AP + u*AT_BP + c4*4)*4u,
                  &g_v[(rowbase + u)*CCH + c0 + c4*4]);
    }
    CP_COMMIT();

    float acc[3][4][4];
    #pragma unroll
    for (int mt = 0; mt < 3; mt++)
        #pragma unroll
        for (int nt = 0; nt < 4; nt++)
            #pragma unroll
            for (int i = 0; i < 4; i++) acc[mt][nt][i] = 0.f;

    CP_WAIT(1);
    __syncthreads();
    #pragma unroll
    for (int phase = 0; phase < 2; phase++) {
        if (phase == 1) { CP_WAIT(0); __syncthreads(); }
        #pragma unroll
        for (int ks6 = 0; ks6 < 6; ks6++) {
            const int ks = phase * 6 + ks6;
            const int k0 = ks * 8;
            uint32_t a[3][4];
            #pragma unroll
            for (int mt = 0; mt < 3; mt++)
                ldsm4(a[mt][0], a[mt][1], a[mt][2], a[mt][3],
                      sbase + (uint32_t)((wm*48 + mt*16 + a_row) * AT_AP + k0 + a_k) * 4u);
            uint32_t bf[4][2];
            #pragma unroll
            for (int nt = 0; nt < 4; nt++) {
                const int col = wn * 32 + nt * 8 + gid;
                bf[nt][0] = __float_as_uint(Bs[(k0 + tg)     * AT_BP + col]);
                bf[nt][1] = __float_as_uint(Bs[(k0 + tg + 4) * AT_BP + col]);
            }
            #pragma unroll
            for (int mt = 0; mt < 3; mt++)
                #pragma unroll
                for (int nt = 0; nt < 4; nt++)
                    mma_tf32(acc[mt][nt][0], acc[mt][nt][1], acc[mt][nt][2], acc[mt][nt][3],
                             a[mt][0], a[mt][1], a[mt][2], a[mt][3],
                             bf[nt][0], bf[nt][1]);
        }
    }

    const float gm = *gamma;
    #pragma unroll
    for (int mt = 0; mt < 3; mt++) {
        const int row0 = wm * 48 + mt * 16 + gid;
        #pragma unroll
        for (int nt = 0; nt < 4; nt++) {
            const int col = c0 + wn * 32 + nt * 8 + tg * 2;
            size_t o0 = (rowbase + row0)*CCH + col;
            size_t o1 = (rowbase + row0 + 8)*CCH + col;
            float2 yv0 = *reinterpret_cast<const float2*>(&g_yv[o0]);
            float2 yv1 = *reinterpret_cast<const float2*>(&g_yv[o1]);
            float2 x0  = *reinterpret_cast<const float2*>(&x[o0]);
            float2 x1  = *reinterpret_cast<const float2*>(&x[o1]);
            float2 r0, r1;
            r0.x = fmaf(acc[mt][nt][0] + yv0.x, gm, x0.x);
            r0.y = fmaf(acc[mt][nt][1] + yv0.y, gm, x0.y);
            r1.x = fmaf(acc[mt][nt][2] + yv1.x, gm, x1.x);
            r1.y = fmaf(acc[mt][nt][3] + yv1.y, gm, x1.y);
            *reinterpret_cast<float2*>(&out[o0]) = r0;
            *reinterpret_cast<float2*>(&out[o1]) = r1;
        }
    }
}

// ---------------------------------------------------------------------------
extern "C" void kernel_launch(void* const* d_in, const int* in_sizes, int n_in,
                              void* d_out, int out_size)
{
    const float* x     = (const float*)d_in[0];
    const float* Wq    = (const float*)d_in[1];
    const float* bq    = (const float*)d_in[2];
    const float* Wk    = (const float*)d_in[3];
    const float* bk    = (const float*)d_in[4];
    const float* Wv    = (const float*)d_in[5];
    const float* bv    = (const float*)d_in[6];
    const float* gamma = (const float*)d_in[7];
    float* out = (float*)d_out;

    float *qkp, *vp, *xt, *wvt, *wqkt, *bqk;
    cudaGetSymbolAddress((void**)&qkp,  g_qk);
    cudaGetSymbolAddress((void**)&vp,   g_v);
    cudaGetSymbolAddress((void**)&xt,   g_xt);
    cudaGetSymbolAddress((void**)&wvt,  g_wvt);
    cudaGetSymbolAddress((void**)&wqkt, g_wqkt);
    cudaGetSymbolAddress((void**)&bqk,  g_bqk);

    cudaFuncSetAttribute(proj_mma,         cudaFuncAttributeMaxDynamicSharedMemorySize, P_SMEM);
    cudaFuncSetAttribute(score_mma<true>,  cudaFuncAttributeMaxDynamicSharedMemorySize, SC_SMEM);
    cudaFuncSetAttribute(score_mma<false>, cudaFuncAttributeMaxDynamicSharedMemorySize, SC_SMEM);
    cudaFuncSetAttribute(yv_mma,           cudaFuncAttributeMaxDynamicSharedMemorySize, AT_SMEM);
    cudaFuncSetAttribute(yh_mma,           cudaFuncAttributeMaxDynamicSharedMemorySize, AT_SMEM);

    // Pre-round + transpose weights
    round_tf32_kernel<<<(NPOS*CCH/4 + 255)/256, 256>>>(x, xt, (size_t)NPOS*CCH/4);
    prep_wv_kernel<<<(CCH*CCH + 255)/256, 256>>>(Wv);
    prep_qk_kernel<<<(128*CCH + 255)/256, 256>>>(Wq, Wk, bq, bk);

    // Projections (outputs tf32-rounded)
    proj_mma<<<dim3(CCH/128, NPOS/128), 256, P_SMEM>>>(xt, wvt,  bv,  vp,  CCH);
    proj_mma<<<dim3(1,       NPOS/128), 256, P_SMEM>>>(xt, wqkt, bqk, qkp, 128);

    // Scores on mma (raw, diag masked in sv)
    score_mma<true> <<<dim3(WW, BB), 256, SC_SMEM>>>();
    score_mma<false><<<dim3(HH, BB), 256, SC_SMEM>>>();

    // Softmax (probs tf32-rounded)
    softmax_kernel<<<NPOS/4, 128>>>();

    // Apply
    yv_mma<<<dim3(4, WW, BB), 256, AT_SMEM>>>();
    yh_mma<<<dim3(4, HH, BB), 256, AT_SMEM>>>(x, gamma, out);
}

// round 15
// speedup vs baseline: 1.4029x; 1.0715x over previous
#include <cuda_runtime.h>
#include <math.h>
#include <stdint.h>

// Problem dims
#define BB   8
#define HH   96
#define WW   96
#define CCH  512
#define DD   64
#define LL   192
#define NPOS (BB*HH*WW)   // 73728

// ---------------------------------------------------------------------------
// Scratch (device globals)
// ---------------------------------------------------------------------------
__device__ float g_qk[(size_t)NPOS*128];    // q | k packed, tf32-rounded
__device__ float g_v [(size_t)NPOS*CCH];    // tf32-rounded
__device__ float g_S [(size_t)NPOS*LL];     // scores -> probs (in place)
__device__ float g_yv[(size_t)NPOS*CCH];
__device__ float g_wvt [(size_t)CCH*CCH];   // Wv^T  [M=512][K=512], tf32-rounded
__device__ float g_wqkt[(size_t)128*CCH];   // [Wq|Wk]^T [128][512], tf32-rounded
__device__ float g_bqk [128];

// ---------------------------------------------------------------------------
// Helpers (baseline PTX, sm_80+)
// ---------------------------------------------------------------------------
__device__ __forceinline__ uint32_t smem_u32(const void* p) {
    uint32_t a;
    asm("{ .reg .u64 t; cvta.to.shared.u64 t, %1; cvt.u32.u64 %0, t; }" : "=r"(a) : "l"(p));
    return a;
}
__device__ __forceinline__ uint32_t f2tf32(float f) {
    uint32_t r;
    asm("cvt.rna.tf32.f32 %0, %1;" : "=r"(r) : "f"(f));
    return r;
}
__device__ __forceinline__ uint32_t bits2tf32(uint32_t b) {
    uint32_t r;
    asm("cvt.rna.tf32.f32 %0, %1;" : "=r"(r) : "f"(__uint_as_float(b)));
    return r;
}
__device__ __forceinline__ void mma_tf32(
    float& c0, float& c1, float& c2, float& c3,
    uint32_t a0, uint32_t a1, uint32_t a2, uint32_t a3,
    uint32_t b0, uint32_t b1)
{
    asm volatile(
        "mma.sync.aligned.m16n8k8.row.col.f32.tf32.tf32.f32 "
        "{%0,%1,%2,%3}, {%4,%5,%6,%7}, {%8,%9}, {%0,%1,%2,%3};"
        : "+f"(c0), "+f"(c1), "+f"(c2), "+f"(c3)
        : "r"(a0), "r"(a1), "r"(a2), "r"(a3), "r"(b0), "r"(b1));
}
__device__ __forceinline__ void ldsm4(uint32_t& r0, uint32_t& r1, uint32_t& r2, uint32_t& r3, uint32_t a) {
    asm volatile("ldmatrix.sync.aligned.m8n8.x4.shared.b16 {%0,%1,%2,%3}, [%4];"
        : "=r"(r0), "=r"(r1), "=r"(r2), "=r"(r3) : "r"(a));
}
__device__ __forceinline__ void ldsm2(uint32_t& r0, uint32_t& r1, uint32_t a) {
    asm volatile("ldmatrix.sync.aligned.m8n8.x2.shared.b16 {%0,%1}, [%2];"
        : "=r"(r0), "=r"(r1) : "r"(a));
}
__device__ __forceinline__ void cpasync16(uint32_t dst, const void* src) {
    asm volatile("cp.async.cg.shared.global [%0], [%1], 16;" :: "r"(dst), "l"(src));
}
#define CP_COMMIT() asm volatile("cp.async.commit_group;" ::: "memory")
#define CP_WAIT(n)  asm volatile("cp.async.wait_group %0;" :: "n"(n) : "memory")

// ---------------------------------------------------------------------------
// P1: transpose + round Wv: Wt[m][k] = rnd(W[k*M + m]),  M=512
// ---------------------------------------------------------------------------
__global__ __launch_bounds__(256) void prep_wv_kernel(const float* __restrict__ W) {
    int idx = blockIdx.x * 256 + threadIdx.x;
    if (idx >= CCH * CCH) return;
    int m = idx >> 9, k = idx & 511;
    g_wvt[idx] = __uint_as_float(f2tf32(W[(size_t)k * CCH + m]));
}

// P2: build transposed rounded [Wq|Wk]^T [128][512] and bias
__global__ __launch_bounds__(256) void prep_qk_kernel(
    const float* __restrict__ Wq, const float* __restrict__ Wk,
    const float* __restrict__ bq, const float* __restrict__ bk)
{
    int idx = blockIdx.x * 256 + threadIdx.x;
    if (idx < 128 * CCH) {
        int j = idx >> 9, k = idx & 511;
        float v = (j < 64) ? Wq[(size_t)k * 64 + j] : Wk[(size_t)k * 64 + (j - 64)];
        g_wqkt[idx] = __uint_as_float(f2tf32(v));
    }
    if (blockIdx.x == 0 && threadIdx.x < 128) {
        int j = threadIdx.x;
        g_bqk[j] = (j < 64) ? bq[j] : bk[j - 64];
    }
}

// ---------------------------------------------------------------------------
// K1: tf32 projection GEMM, ldmatrix feed, 3-stage cp.async pipeline.
//   A = raw x (fp32); fragments rounded to tf32 in-register post-ldmatrix.
//   C[r, n0+c] = sum_k rnd(X[r,k]) * Wt[n0+c, k] + bias[c]
// ---------------------------------------------------------------------------
#define PJ_P 36
#define PJ_TSZ (128*PJ_P)
#define PJ_STG (2*PJ_TSZ)          // A+B per stage (floats)
#define P_SMEM (3*PJ_STG*4)        // 110592 B

__global__ __launch_bounds__(256) void proj_mma(
    const float* __restrict__ X, const float* __restrict__ Wt,
    const float* __restrict__ bias, float* __restrict__ C, int M)
{
    constexpr int BK = 32, NCH = CCH / BK;   // 16 chunks
    extern __shared__ float sm[];
    const uint32_t sbase = smem_u32(sm);
    const int tid = threadIdx.x;
    const int wid = tid >> 5, lane = tid & 31;
    const int gid = lane >> 2, tg = lane & 3;
    const int wm = wid >> 2, wn = wid & 3;
    const int rowBase = blockIdx.y * 128;
    const int n0 = blockIdx.x * 128;

    const int a_row = (lane & 15), a_k = (lane >> 4) * 4;
    const int b_row = ((lane >> 4) * 8) + (lane & 7);
    const int b_k   = ((lane >> 3) & 1) * 4;

    float acc[4][4][4];
    #pragma unroll
    for (int mt = 0; mt < 4; mt++)
        #pragma unroll
        for (int nt = 0; nt < 4; nt++)
            #pragma unroll
            for (int i = 0; i < 4; i++) acc[mt][nt][i] = 0.f;

    auto issue = [&](int ch) {
        const int kc = ch * BK;
        const int buf = ch % 3;
        const uint32_t abase = sbase + (uint32_t)(buf * PJ_STG) * 4u;
        const uint32_t bbase = abase + (uint32_t)PJ_TSZ * 4u;
        #pragma unroll
        for (int i = 0; i < 4; i++) {
            int idx = tid + i * 256;
            int r = idx >> 3, c4 = idx & 7;
            cpasync16(abase + (uint32_t)(r * PJ_P + c4 * 4) * 4u,
                      &X[(size_t)(rowBase + r) * CCH + kc + c4 * 4]);
            cpasync16(bbase + (uint32_t)(r * PJ_P + c4 * 4) * 4u,
                      &Wt[(size_t)(n0 + r) * CCH + kc + c4 * 4]);
        }
        CP_COMMIT();
    };

    issue(0);
    issue(1);
    for (int ch = 0; ch < NCH; ch++) {
        if (ch < NCH - 1) { CP_WAIT(1); }
        else              { CP_WAIT(0); }
        __syncthreads();
        if (ch + 2 < NCH) issue(ch + 2);   // safe: all warps past compute(ch-1)

        const int buf = ch % 3;
        const uint32_t Ab = sbase + (uint32_t)(buf * PJ_STG) * 4u;
        const uint32_t Bb = Ab + (uint32_t)PJ_TSZ * 4u;
        #pragma unroll
        for (int ks = 0; ks < 4; ks++) {
            const int k0 = ks * 8;
            uint32_t a[4][4];
            #pragma unroll
            for (int mt = 0; mt < 4; mt++) {
                ldsm4(a[mt][0], a[mt][1], a[mt][2], a[mt][3],
                      Ab + (uint32_t)((wm*64 + mt*16 + a_row) * PJ_P + k0 + a_k) * 4u);
                #pragma unroll
                for (int i = 0; i < 4; i++) a[mt][i] = bits2tf32(a[mt][i]);
            }
            uint32_t b[4][2];
            #pragma unroll
            for (int pr = 0; pr < 2; pr++)
                ldsm4(b[pr*2][0], b[pr*2][1], b[pr*2+1][0], b[pr*2+1][1],
                      Bb + (uint32_t)((wn*32 + pr*16 + b_row) * PJ_P + k0 + b_k) * 4u);
            #pragma unroll
            for (int mt = 0; mt < 4; mt++)
                #pragma unroll
                for (int nt = 0; nt < 4; nt++)
                    mma_tf32(acc[mt][nt][0], acc[mt][nt][1], acc[mt][nt][2], acc[mt][nt][3],
                             a[mt][0], a[mt][1], a[mt][2], a[mt][3],
                             b[nt][0], b[nt][1]);
        }
    }

    #pragma unroll
    for (int mt = 0; mt < 4; mt++) {
        const int row = rowBase + wm * 64 + mt * 16 + gid;
        #pragma unroll
        for (int nt = 0; nt < 4; nt++) {
            const int col = n0 + wn * 32 + nt * 8 + tg * 2;
            const float b0 = bias[col], b1 = bias[col + 1];
            C[(size_t)row * M + col]           = __uint_as_float(f2tf32(acc[mt][nt][0] + b0));
            C[(size_t)row * M + col + 1]       = __uint_as_float(f2tf32(acc[mt][nt][1] + b1));
            C[(size_t)(row + 8) * M + col]     = __uint_as_float(f2tf32(acc[mt][nt][2] + b0));
            C[(size_t)(row + 8) * M + col + 1] = __uint_as_float(f2tf32(acc[mt][nt][3] + b1));
        }
    }
}

// ---------------------------------------------------------------------------
// K2/K3: score GEMMs, ldmatrix feed on both operands.
// ---------------------------------------------------------------------------
#define SC_P 68
#define SC_SMEM (2*96*SC_P*4)    // 52224

template<bool SV>
__global__ __launch_bounds__(256) void score_mma() {
    extern __shared__ float sm[];
    const uint32_t sbase = smem_u32(sm);
    const uint32_t Qb = sbase;
    const uint32_t Kb = sbase + (uint32_t)(96*SC_P)*4u;
    const int b = blockIdx.y, line = blockIdx.x;
    const int tid = threadIdx.x;
    const int wid = tid >> 5, lane = tid & 31;
    const int gid = lane >> 2, tg = lane & 3;
    const int wm = wid >> 2, wn = wid & 3;

    const int a_row = (lane & 15), a_k = (lane >> 4) * 4;
    const int b_row = ((lane >> 4) * 8) + (lane & 7);
    const int b_k   = ((lane >> 3) & 1) * 4;
    const int b2_row = (lane & 7);
    const int b2_k   = ((lane >> 3) & 1) * 4;

    for (int i = tid; i < 96*16; i += 256) {
        int r = i >> 4, c4 = i & 15;
        size_t src = SV
            ? ((size_t)((b*HH + r)*WW) + line)*128
            : ((size_t)((b*HH + line)*WW) + r)*128;
        cpasync16(Qb + (uint32_t)(r*SC_P + c4*4)*4u, &g_qk[src + c4*4]);
        cpasync16(Kb + (uint32_t)(r*SC_P + c4*4)*4u, &g_qk[src + 64 + c4*4]);
    }
    CP_COMMIT(); CP_WAIT(0);
    __syncthreads();

    float acc[3][3][4];
    #pragma unroll
    for (int mt = 0; mt < 3; mt++)
        #pragma unroll
        for (int nt = 0; nt < 3; nt++)
            #pragma unroll
            for (int i = 0; i < 4; i++) acc[mt][nt][i] = 0.f;

    #pragma unroll
    for (int ks = 0; ks < 8; ks++) {
        const int k0 = ks * 8;
        uint32_t a[3][4];
        #pragma unroll
        for (int mt = 0; mt < 3; mt++)
            ldsm4(a[mt][0], a[mt][1], a[mt][2], a[mt][3],
                  Qb + (uint32_t)((wm*48 + mt*16 + a_row) * SC_P + k0 + a_k) * 4u);
        uint32_t bf[3][2];
        ldsm4(bf[0][0], bf[0][1], bf[1][0], bf[1][1],
              Kb + (uint32_t)((wn*24 + b_row) * SC_P + k0 + b_k) * 4u);
        ldsm2(bf[2][0], bf[2][1],
              Kb + (uint32_t)((wn*24 + 16 + b2_row) * SC_P + k0 + b2_k) * 4u);
        #pragma unroll
        for (int mt = 0; mt < 3; mt++)
            #pragma unroll
            for (int nt = 0; nt < 3; nt++)
                mma_tf32(acc[mt][nt][0], acc[mt][nt][1], acc[mt][nt][2], acc[mt][nt][3],
                         a[mt][0], a[mt][1], a[mt][2], a[mt][3],
                         bf[nt][0], bf[nt][1]);
    }

    #pragma unroll
    for (int mt = 0; mt < 3; mt++) {
        const int r0 = wm * 48 + mt * 16 + gid;
        #pragma unroll
        for (int nt = 0; nt < 3; nt++) {
            const int c0 = wn * 24 + nt * 8 + tg * 2;
            #pragma unroll
            for (int half = 0; half < 2; half++) {
                const int r = r0 + half * 8;
                size_t base = SV
                    ? ((size_t)((b*HH + r)*WW) + line)*LL
                    : ((size_t)((b*HH + line)*WW) + r)*LL + 96;
                float v0 = acc[mt][nt][half*2],  v1 = acc[mt][nt][half*2 + 1];
                if (SV) {
                    if (c0     == r) v0 = -1e30f;
                    if (c0 + 1 == r) v1 = -1e30f;
                }
                g_S[base + c0]     = v0;
                g_S[base + c0 + 1] = v1;
            }
        }
    }
}

// ---------------------------------------------------------------------------
// K4: softmax over 192, in place; writes tf32-rounded probs.
// ---------------------------------------------------------------------------
__global__ __launch_bounds__(128) void softmax_kernel() {
    const int lane = threadIdx.x & 31;
    const size_t pos = (size_t)blockIdx.x * 4 + (threadIdx.x >> 5);
    float* s = g_S + pos * LL;
    float v[6];
    float m = -3.4e38f;
    #pragma unroll
    for (int i = 0; i < 6; i++) { v[i] = s[lane + 32*i]; m = fmaxf(m, v[i]); }
    #pragma unroll
    for (int o = 16; o; o >>= 1) m = fmaxf(m, __shfl_xor_sync(0xffffffffu, m, o));
    float sum = 0.f;
    #pragma unroll
    for (int i = 0; i < 6; i++) { v[i] = expf(v[i] - m); sum += v[i]; }
    #pragma unroll
    for (int o = 16; o; o >>= 1) sum += __shfl_xor_sync(0xffffffffu, sum, o);
    const float inv = 1.f / sum;
    #pragma unroll
    for (int i = 0; i < 6; i++)
        s[lane + 32*i] = __uint_as_float(f2tf32(v[i] * inv));
}

// ---------------------------------------------------------------------------
// K5/K6: attention apply. A via ldmatrix; B scalar LDS. Two-group load:
//   group0 = A + B rows 0..47 (covers ks 0..5), group1 = B rows 48..95.
// ---------------------------------------------------------------------------
#define AT_AP 100
#define AT_BP 136
#define AT_SMEM ((96*AT_AP + 96*AT_BP)*4)   // 90624

__global__ __launch_bounds__(256) void yv_mma() {
    extern __shared__ float sm[];
    float* Bs = sm + 96*AT_AP;
    const uint32_t sbase = smem_u32(sm);
    const int b = blockIdx.z, w = blockIdx.y, c0 = blockIdx.x * 128;
    const int tid = threadIdx.x;
    const int wid = tid >> 5, lane = tid & 31;
    const int gid = lane >> 2, tg = lane & 3;
    const int wm = wid >> 2, wn = wid & 3;
    const int a_row = (lane & 15), a_k = (lane >> 4) * 4;

    // group 0: A + B rows 0..47
    for (int i = tid; i < 96*24; i += 256) {
        int h = i / 24, c4 = i % 24;
        cpasync16(sbase + (uint32_t)(h*AT_AP + c4*4)*4u,
                  &g_S[((size_t)((b*HH + h)*WW) + w)*LL + c4*4]);
    }
    for (int i = tid; i < 48*32; i += 256) {
        int g = i >> 5, c4 = i & 31;
        cpasync16(sbase + (uint32_t)(96*AT_AP + g*AT_BP + c4*4)*4u,
                  &g_v[((size_t)((b*HH + g)*WW) + w)*CCH + c0 + c4*4]);
    }
    CP_COMMIT();
    // group 1: B rows 48..95
    for (int i = tid; i < 48*32; i += 256) {
        int g = (i >> 5) + 48, c4 = i & 31;
        cpasync16(sbase + (uint32_t)(96*AT_AP + g*AT_BP + c4*4)*4u,
                  &g_v[((size_t)((b*HH + g)*WW) + w)*CCH + c0 + c4*4]);
    }
    CP_COMMIT();

    float acc[3][4][4];
    #pragma unroll
    for (int mt = 0; mt < 3; mt++)
        #pragma unroll
        for (int nt = 0; nt < 4; nt++)
            #pragma unroll
            for (int i = 0; i < 4; i++) acc[mt][nt][i] = 0.f;

    CP_WAIT(1);
    __syncthreads();
    #pragma unroll
    for (int phase = 0; phase < 2; phase++) {
        if (phase == 1) { CP_WAIT(0); __syncthreads(); }
        #pragma unroll
        for (int ks6 = 0; ks6 < 6; ks6++) {
            const int ks = phase * 6 + ks6;
            const int k0 = ks * 8;
            uint32_t a[3][4];
            #pragma unroll
            for (int mt = 0; mt < 3; mt++)
                ldsm4(a[mt][0], a[mt][1], a[mt][2], a[mt][3],
                      sbase + (uint32_t)((wm*48 + mt*16 + a_row) * AT_AP + k0 + a_k) * 4u);
            uint32_t bf[4][2];
            #pragma unroll
            for (int nt = 0; nt < 4; nt++) {
                const int col = wn * 32 + nt * 8 + gid;
                bf[nt][0] = __float_as_uint(Bs[(k0 + tg)     * AT_BP + col]);
                bf[nt][1] = __float_as_uint(Bs[(k0 + tg + 4) * AT_BP + col]);
            }
            #pragma unroll
            for (int mt = 0; mt < 3; mt++)
                #pragma unroll
                for (int nt = 0; nt < 4; nt++)
                    mma_tf32(acc[mt][nt][0], acc[mt][nt][1], acc[mt][nt][2], acc[mt][nt][3],
                             a[mt][0], a[mt][1], a[mt][2], a[mt][3],
                             bf[nt][0], bf[nt][1]);
        }
    }

    #pragma unroll
    for (int mt = 0; mt < 3; mt++) {
        const int row0 = wm * 48 + mt * 16 + gid;
        #pragma unroll
        for (int nt = 0; nt < 4; nt++) {
            const int col = c0 + wn * 32 + nt * 8 + tg * 2;
            size_t o0 = ((size_t)((b*HH + row0)*WW) + w)*CCH + col;
            size_t o1 = ((size_t)((b*HH + row0 + 8)*WW) + w)*CCH + col;
            *reinterpret_cast<float2*>(&g_yv[o0]) = make_float2(acc[mt][nt][0], acc[mt][nt][1]);
            *reinterpret_cast<float2*>(&g_yv[o1]) = make_float2(acc[mt][nt][2], acc[mt][nt][3]);
        }
    }
}

__global__ __launch_bounds__(256) void yh_mma(
    const float* __restrict__ x, const float* __restrict__ gamma,
    float* __restrict__ out)
{
    extern __shared__ float sm[];
    float* Bs = sm + 96*AT_AP;
    const uint32_t sbase = smem_u32(sm);
    const int b = blockIdx.z, h = blockIdx.y, c0 = blockIdx.x * 128;
    const int tid = threadIdx.x;
    const int wid = tid >> 5, lane = tid & 31;
    const int gid = lane >> 2, tg = lane & 3;
    const int wm = wid >> 2, wn = wid & 3;
    const int a_row = (lane & 15), a_k = (lane >> 4) * 4;
    const size_t rowbase = (size_t)(b*HH + h)*WW;

    for (int i = tid; i < 96*24; i += 256) {
        int r = i / 24, c4 = i % 24;
        cpasync16(sbase + (uint32_t)(r*AT_AP + c4*4)*4u,
                  &g_S[(rowbase + r)*LL + 96 + c4*4]);
    }
    for (int i = tid; i < 48*32; i += 256) {
        int u = i >> 5, c4 = i & 31;
        cpasync16(sbase + (uint32_t)(96*AT_AP + u*AT_BP + c4*4)*4u,
                  &g_v[(rowbase + u)*CCH + c0 + c4*4]);
    }
    CP_COMMIT();
    for (int i = tid; i < 48*32; i += 256) {
        int u = (i >> 5) + 48, c4 = i & 31;
        cpasync16(sbase + (uint32_t)(96*AT_AP + u*AT_BP + c4*4)*4u,
                  &g_v[(rowbase + u)*CCH + c0 + c4*4]);
    }
    CP_COMMIT();

    float acc[3][4][4];
    #pragma unroll
    for (int mt = 0; mt < 3; mt++)
        #pragma unroll
        for (int nt = 0; nt < 4; nt++)
            #pragma unroll
            for (int i = 0; i < 4; i++) acc[mt][nt][i] = 0.f;

    CP_WAIT(1);
    __syncthreads();
    #pragma unroll
    for (int phase = 0; phase < 2; phase++) {
        if (phase == 1) { CP_WAIT(0); __syncthreads(); }
        #pragma unroll
        for (int ks6 = 0; ks6 < 6; ks6++) {
            const int ks = phase * 6 + ks6;
            const int k0 = ks * 8;
            uint32_t a[3][4];
            #pragma unroll
            for (int mt = 0; mt < 3; mt++)
                ldsm4(a[mt][0], a[mt][1], a[mt][2], a[mt][3],
                      sbase + (uint32_t)((wm*48 + mt*16 + a_row) * AT_AP + k0 + a_k) * 4u);
            uint32_t bf[4][2];
            #pragma unroll
            for (int nt = 0; nt < 4; nt++) {
                const int col = wn * 32 + nt * 8 + gid;
                bf[nt][0] = __float_as_uint(Bs[(k0 + tg)     * AT_BP + col]);
                bf[nt][1] = __float_as_uint(Bs[(k0 + tg + 4) * AT_BP + col]);
            }
            #pragma unroll
            for (int mt = 0; mt < 3; mt++)
                #pragma unroll
                for (int nt = 0; nt < 4; nt++)
                    mma_tf32(acc[mt][nt][0], acc[mt][nt][1], acc[mt][nt][2], acc[mt][nt][3],
                             a[mt][0], a[mt][1], a[mt][2], a[mt][3],
                             bf[nt][0], bf[nt][1]);
        }
    }

    const float gm = *gamma;
    #pragma unroll
    for (int mt = 0; mt < 3; mt++) {
        const int row0 = wm * 48 + mt * 16 + gid;
        #pragma unroll
        for (int nt = 0; nt < 4; nt++) {
            const int col = c0 + wn * 32 + nt * 8 + tg * 2;
            size_t o0 = (rowbase + row0)*CCH + col;
            size_t o1 = (rowbase + row0 + 8)*CCH + col;
            float2 yv0 = *reinterpret_cast<const float2*>(&g_yv[o0]);
            float2 yv1 = *reinterpret_cast<const float2*>(&g_yv[o1]);
            float2 x0  = *reinterpret_cast<const float2*>(&x[o0]);
            float2 x1  = *reinterpret_cast<const float2*>(&x[o1]);
            float2 r0, r1;
            r0.x = fmaf(acc[mt][nt][0] + yv0.x, gm, x0.x);
            r0.y = fmaf(acc[mt][nt][1] + yv0.y, gm, x0.y);
            r1.x = fmaf(acc[mt][nt][2] + yv1.x, gm, x1.x);
            r1.y = fmaf(acc[mt][nt][3] + yv1.y, gm, x1.y);
            *reinterpret_cast<float2*>(&out[o0]) = r0;
            *reinterpret_cast<float2*>(&out[o1]) = r1;
        }
    }
}

// ---------------------------------------------------------------------------
extern "C" void kernel_launch(void* const* d_in, const int* in_sizes, int n_in,
                              void* d_out, int out_size)
{
    const float* x     = (const float*)d_in[0];
    const float* Wq    = (const float*)d_in[1];
    const float* bq    = (const float*)d_in[2];
    const float* Wk    = (const float*)d_in[3];
    const float* bk    = (const float*)d_in[4];
    const float* Wv    = (const float*)d_in[5];
    const float* bv    = (const float*)d_in[6];
    const float* gamma = (const float*)d_in[7];
    float* out = (float*)d_out;

    float *qkp, *vp, *wvt, *wqkt, *bqk;
    cudaGetSymbolAddress((void**)&qkp,  g_qk);
    cudaGetSymbolAddress((void**)&vp,   g_v);
    cudaGetSymbolAddress((void**)&wvt,  g_wvt);
    cudaGetSymbolAddress((void**)&wqkt, g_wqkt);
    cudaGetSymbolAddress((void**)&bqk,  g_bqk);

    cudaFuncSetAttribute(proj_mma,         cudaFuncAttributeMaxDynamicSharedMemorySize, P_SMEM);
    cudaFuncSetAttribute(score_mma<true>,  cudaFuncAttributeMaxDynamicSharedMemorySize, SC_SMEM);
    cudaFuncSetAttribute(score_mma<false>, cudaFuncAttributeMaxDynamicSharedMemorySize, SC_SMEM);
    cudaFuncSetAttribute(yv_mma,           cudaFuncAttributeMaxDynamicSharedMemorySize, AT_SMEM);
    cudaFuncSetAttribute(yh_mma,           cudaFuncAttributeMaxDynamicSharedMemorySize, AT_SMEM);

    // Side stream + events: created once on the (uncaptured) correctness call,
    // reused by capture. Same launch DAG every call.
    static cudaStream_t s2 = nullptr;
    static cudaEvent_t ev_fork = nullptr, ev_join = nullptr;
    if (s2 == nullptr) {
        cudaStreamCreateWithFlags(&s2, cudaStreamNonBlocking);
        cudaEventCreateWithFlags(&ev_fork, cudaEventDisableTiming);
        cudaEventCreateWithFlags(&ev_join, cudaEventDisableTiming);
    }

    // Weight prep on main stream
    prep_wv_kernel<<<(CCH*CCH + 255)/256, 256>>>(Wv);
    prep_qk_kernel<<<(128*CCH + 255)/256, 256>>>(Wq, Wk, bq, bk);

    // Fork: q/k chain on s2, concurrent with v projection on stream 0
    cudaEventRecord(ev_fork, 0);
    cudaStreamWaitEvent(s2, ev_fork, 0);

    proj_mma<<<dim3(1, NPOS/128), 256, P_SMEM, s2>>>(x, wqkt, bqk, qkp, 128);
    score_mma<true> <<<dim3(WW, BB), 256, SC_SMEM, s2>>>();
    score_mma<false><<<dim3(HH, BB), 256, SC_SMEM, s2>>>();
    softmax_kernel<<<NPOS/4, 128, 0, s2>>>();
    cudaEventRecord(ev_join, s2);

    proj_mma<<<dim3(CCH/128, NPOS/128), 256, P_SMEM>>>(x, wvt, bv, vp, CCH);

    // Join: apply needs both v and probs
    cudaStreamWaitEvent(0, ev_join, 0);
    yv_mma<<<dim3(4, WW, BB), 256, AT_SMEM>>>();
    yh_mma<<<dim3(4, HH, BB), 256, AT_SMEM>>>(x, gamma, out);
}